// round 10
// baseline (speedup 1.0000x reference)
#include <cuda_runtime.h>
#include <cuda_bf16.h>
#include <math_constants.h>

#define Bn  8
#define Sn  1024
#define Dn  1024
#define Hn  16
#define DHn 64
#define Mn  (Bn * Sn)   // 8192

// ---------------------------------------------------------------------------
// Device-global scratch
// ---------------------------------------------------------------------------
__device__ __nv_bfloat16 gin_qh[Mn * Dn], gin_ql[Mn * Dn];
__device__ __nv_bfloat16 gin_kh[Mn * Dn], gin_kl[Mn * Dn];
__device__ __nv_bfloat16 gin_vh[Mn * Dn], gin_vl[Mn * Dn];
__device__ __nv_bfloat16 gWqh[Dn * Dn], gWql[Dn * Dn];
__device__ __nv_bfloat16 gWkh[Dn * Dn], gWkl[Dn * Dn];
__device__ __nv_bfloat16 gWvh[Dn * Dn], gWvl[Dn * Dn];
__device__ __nv_bfloat16 gWoh[Dn * Dn], gWol[Dn * Dn];
__device__ __nv_bfloat16 g_qh[Mn * Dn], g_ql[Mn * Dn];   // [B,H,S,DH]
__device__ __nv_bfloat16 g_kh[Mn * Dn], g_kl[Mn * Dn];
__device__ __nv_bfloat16 g_vh[Mn * Dn], g_vl[Mn * Dn];
__device__ __nv_bfloat16 g_ctxh[Mn * Dn], g_ctxl[Mn * Dn]; // [B,S,D]
__device__ unsigned char g_mask[Bn * Sn * Sn];             // packed mask bytes

// ---------------------------------------------------------------------------
// helpers
// ---------------------------------------------------------------------------
__device__ __forceinline__ unsigned smem_u32(const void* p) {
    return (unsigned)__cvta_generic_to_shared(p);
}
__device__ __forceinline__ void mma16816(float* c, const unsigned* a, const unsigned* b) {
    asm volatile(
        "mma.sync.aligned.m16n8k16.row.col.f32.bf16.bf16.f32 "
        "{%0,%1,%2,%3},{%4,%5,%6,%7},{%8,%9},{%0,%1,%2,%3};\n"
        : "+f"(c[0]), "+f"(c[1]), "+f"(c[2]), "+f"(c[3])
        : "r"(a[0]), "r"(a[1]), "r"(a[2]), "r"(a[3]), "r"(b[0]), "r"(b[1]));
}
__device__ __forceinline__ void ldsm4(unsigned* r, unsigned addr) {
    asm volatile("ldmatrix.sync.aligned.m8n8.x4.shared.b16 {%0,%1,%2,%3},[%4];\n"
                 : "=r"(r[0]), "=r"(r[1]), "=r"(r[2]), "=r"(r[3]) : "r"(addr));
}
__device__ __forceinline__ void ldsm4t(unsigned* r, unsigned addr) {
    asm volatile("ldmatrix.sync.aligned.m8n8.x4.trans.shared.b16 {%0,%1,%2,%3},[%4];\n"
                 : "=r"(r[0]), "=r"(r[1]), "=r"(r[2]), "=r"(r[3]) : "r"(addr));
}
__device__ __forceinline__ void split_pack(float x, float y, unsigned& hi, unsigned& lo) {
    __nv_bfloat16 hx = __float2bfloat16(x);
    __nv_bfloat16 hy = __float2bfloat16(y);
    float rx = x - __bfloat162float(hx);
    float ry = y - __bfloat162float(hy);
    __nv_bfloat162 h; h.x = hx; h.y = hy;
    __nv_bfloat162 l; l.x = __float2bfloat16(rx); l.y = __float2bfloat16(ry);
    hi = *(unsigned*)&h;
    lo = *(unsigned*)&l;
}
// fast 2^y, FMA-only (no MUFU)
__device__ __forceinline__ float exp2p(float y) {
    y = fmaxf(fminf(y, 60.f), -60.f);
    float z = y + 12582912.f;              // 1.5*2^23
    int i = __float_as_int(z) << 23;
    float f = y - (z - 12582912.f);
    float p = 1.3333558e-3f;
    p = fmaf(p, f, 9.6181291e-3f);
    p = fmaf(p, f, 5.5504109e-2f);
    p = fmaf(p, f, 2.4022651e-1f);
    p = fmaf(p, f, 6.9314718e-1f);
    p = fmaf(p, f, 1.0f);
    return __int_as_float(__float_as_int(p) + i);
}
#define CPA16(smem, gmem) asm volatile("cp.async.cg.shared.global [%0], [%1], 16;\n" :: "r"(smem), "l"(gmem))
#define CPA_COMMIT()      asm volatile("cp.async.commit_group;\n")
#define CPA_WAIT0()       asm volatile("cp.async.wait_group 0;\n" ::: "memory")
#define CPA_WAIT1()       asm volatile("cp.async.wait_group 1;\n" ::: "memory")

// ---------------------------------------------------------------------------
// Pre-split kernels + mask pack
// ---------------------------------------------------------------------------
__device__ __forceinline__ void do_split(const float* src, __nv_bfloat16* hi,
                                         __nv_bfloat16* lo, int i) {
    float2 v = ((const float2*)src)[i];
    unsigned h, l;
    split_pack(v.x, v.y, h, l);
    ((unsigned*)hi)[i] = h;
    ((unsigned*)lo)[i] = l;
}
__global__ void split_in3(const float* __restrict__ s0, const float* __restrict__ s1,
                          const float* __restrict__ s2,
                          __nv_bfloat16* h0, __nv_bfloat16* l0,
                          __nv_bfloat16* h1, __nv_bfloat16* l1,
                          __nv_bfloat16* h2, __nv_bfloat16* l2, int n2)
{
    int i = blockIdx.x * blockDim.x + threadIdx.x;
    if (i >= n2) return;
    switch (blockIdx.y) {
        case 0: do_split(s0, h0, l0, i); break;
        case 1: do_split(s1, h1, l1, i); break;
        default: do_split(s2, h2, l2, i); break;
    }
}
__global__ void split_in4(const float* __restrict__ s0, const float* __restrict__ s1,
                          const float* __restrict__ s2, const float* __restrict__ s3,
                          __nv_bfloat16* h0, __nv_bfloat16* l0,
                          __nv_bfloat16* h1, __nv_bfloat16* l1,
                          __nv_bfloat16* h2, __nv_bfloat16* l2,
                          __nv_bfloat16* h3, __nv_bfloat16* l3, int n2)
{
    int i = blockIdx.x * blockDim.x + threadIdx.x;
    if (i >= n2) return;
    switch (blockIdx.y) {
        case 0: do_split(s0, h0, l0, i); break;
        case 1: do_split(s1, h1, l1, i); break;
        case 2: do_split(s2, h2, l2, i); break;
        default: do_split(s3, h3, l3, i); break;
    }
}
__global__ void pack_mask(const int4* __restrict__ m, uchar4* __restrict__ o, int n4)
{
    int i = blockIdx.x * blockDim.x + threadIdx.x;
    if (i < n4) {
        int4 v = m[i];
        o[i] = make_uchar4((unsigned char)(v.x != 0), (unsigned char)(v.y != 0),
                           (unsigned char)(v.z != 0), (unsigned char)(v.w != 0));
    }
}

// ---------------------------------------------------------------------------
// Split-bf16 (3x) GEMM body: CTA tile 256x128, BK=32, 512 threads,
// warp grid 4x4 (warp tile 64x32). Squared warp grid cuts smem crossbar
// traffic per FLOP by 1/3 vs 128x128/8-warp. cp.async double-buffered.
// mode 0: head-split bf16 hi/lo out, scaled. mode 2: plain fp32 out.
// ---------------------------------------------------------------------------
#define GST 80        // bytes per smem row (64B data + 16B pad)
#define A_ST (256 * GST)          // 20480 per A matrix
#define W_ST (128 * GST)          // 10240 per W matrix
#define STAGE_B (2 * A_ST + 2 * W_ST)  // 61440 per stage
#define GEMM_SMEM (2 * STAGE_B)        // 122880

__device__ __forceinline__
void gemm_body(char* dsm,
               const __nv_bfloat16* __restrict__ Ahi, const __nv_bfloat16* __restrict__ Alo,
               const __nv_bfloat16* __restrict__ Whi, const __nv_bfloat16* __restrict__ Wlo,
               const float* __restrict__ bias,
               float* __restrict__ Cf,
               __nv_bfloat16* __restrict__ Ch, __nv_bfloat16* __restrict__ Cl,
               int mode, float scale, int m0, int n0)
{
    const int tid = threadIdx.x;
    const int wid = tid >> 5, lane = tid & 31;
    const int wm = wid & 3, wn = wid >> 2;    // 4x4 warp grid
    const int g = lane >> 2, t = lane & 3;
    const int sub = lane >> 3;

    float c[4][4][4];
    #pragma unroll
    for (int mt = 0; mt < 4; mt++)
        #pragma unroll
        for (int nt = 0; nt < 4; nt++)
            #pragma unroll
            for (int e = 0; e < 4; e++) c[mt][nt][e] = 0.f;

    auto issue = [&](int k0, int buf) {
        char* st = dsm + buf * STAGE_B;
        // A hi/lo: 256 rows x 4 chunks = 1024 chunks each -> 2 per thread
        #pragma unroll
        for (int i = 0; i < 2; i++) {
            int cc = i * 512 + tid;
            int r = cc >> 2, off = cc & 3;
            size_t ga = (size_t)(m0 + r) * Dn + k0 + off * 8;
            unsigned sa = smem_u32(st + r * GST + off * 16);
            CPA16(sa,        Ahi + ga);
            CPA16(sa + A_ST, Alo + ga);
        }
        // W hi/lo: 128 rows x 4 chunks = 512 chunks each -> 1 per thread
        {
            int r = tid >> 2, off = tid & 3;
            size_t gw = (size_t)(n0 + r) * Dn + k0 + off * 8;
            unsigned sw = smem_u32(st + 2 * A_ST + r * GST + off * 16);
            CPA16(sw,        Whi + gw);
            CPA16(sw + W_ST, Wlo + gw);
        }
    };

    issue(0, 0);
    CPA_COMMIT();

    for (int it = 0; it < Dn / 32; it++) {
        CPA_WAIT0();
        __syncthreads();
        if (it + 1 < Dn / 32) { issue((it + 1) * 32, (it + 1) & 1); CPA_COMMIT(); }

        char* st = dsm + (it & 1) * STAGE_B;
        char* sAh = st; char* sAl = st + A_ST;
        char* sWh = st + 2 * A_ST; char* sWl = st + 2 * A_ST + W_ST;

        #pragma unroll
        for (int kt = 0; kt < 2; kt++) {
            unsigned ah[4][4], al[4][4], bh[4][2], bl[4][2];
            #pragma unroll
            for (int mt = 0; mt < 4; mt++) {
                int r = wm * 64 + mt * 16 + (lane & 7) + (sub & 1) * 8;
                int kb = kt * 32 + (sub >> 1) * 16;
                ldsm4(ah[mt], smem_u32(sAh + r * GST + kb));
                ldsm4(al[mt], smem_u32(sAl + r * GST + kb));
            }
            #pragma unroll
            for (int ntp = 0; ntp < 2; ntp++) {
                int r = wn * 32 + (ntp * 2 + (sub >> 1)) * 8 + (lane & 7);
                int kb = kt * 32 + (sub & 1) * 16;
                unsigned tmp[4];
                ldsm4(tmp, smem_u32(sWh + r * GST + kb));
                bh[2 * ntp][0] = tmp[0]; bh[2 * ntp][1] = tmp[1];
                bh[2 * ntp + 1][0] = tmp[2]; bh[2 * ntp + 1][1] = tmp[3];
                ldsm4(tmp, smem_u32(sWl + r * GST + kb));
                bl[2 * ntp][0] = tmp[0]; bl[2 * ntp][1] = tmp[1];
                bl[2 * ntp + 1][0] = tmp[2]; bl[2 * ntp + 1][1] = tmp[3];
            }
            #pragma unroll
            for (int mt = 0; mt < 4; mt++)
                #pragma unroll
                for (int nt = 0; nt < 4; nt++)
                    mma16816(c[mt][nt], ah[mt], bh[nt]);
            #pragma unroll
            for (int mt = 0; mt < 4; mt++)
                #pragma unroll
                for (int nt = 0; nt < 4; nt++)
                    mma16816(c[mt][nt], ah[mt], bl[nt]);
            #pragma unroll
            for (int mt = 0; mt < 4; mt++)
                #pragma unroll
                for (int nt = 0; nt < 4; nt++)
                    mma16816(c[mt][nt], al[mt], bh[nt]);
        }
    }

    #pragma unroll
    for (int mt = 0; mt < 4; mt++) {
        #pragma unroll
        for (int nt = 0; nt < 4; nt++) {
            const int row = m0 + wm * 64 + mt * 16 + g;
            const int col = n0 + wn * 32 + nt * 8 + 2 * t;
            const float b0 = bias[col], b1 = bias[col + 1];
            #pragma unroll
            for (int half = 0; half < 2; half++) {
                const int r = row + half * 8;
                const float v0 = (c[mt][nt][half * 2 + 0] + b0) * scale;
                const float v1 = (c[mt][nt][half * 2 + 1] + b1) * scale;
                if (mode == 2) {
                    *(float2*)(Cf + (size_t)r * Dn + col) = make_float2(v0, v1);
                } else {
                    const int bb = r >> 10, s = r & 1023;
                    const int hh = col >> 6, d = col & 63;
                    size_t idx = (((size_t)(bb * Hn + hh) * Sn + s) * DHn) + d;
                    unsigned hw, lw;
                    split_pack(v0, v1, hw, lw);
                    *(unsigned*)(Ch + idx) = hw;
                    *(unsigned*)(Cl + idx) = lw;
                }
            }
        }
    }
}

// fused Q/K/V projections: blockIdx.z selects the matmul
__global__ __launch_bounds__(512, 1)
void gemm_qkv(const __nv_bfloat16* Ah0, const __nv_bfloat16* Al0,
              const __nv_bfloat16* Ah1, const __nv_bfloat16* Al1,
              const __nv_bfloat16* Ah2, const __nv_bfloat16* Al2,
              const __nv_bfloat16* Wh0, const __nv_bfloat16* Wl0,
              const __nv_bfloat16* Wh1, const __nv_bfloat16* Wl1,
              const __nv_bfloat16* Wh2, const __nv_bfloat16* Wl2,
              const float* b0, const float* b1, const float* b2,
              __nv_bfloat16* Ch0, __nv_bfloat16* Cl0,
              __nv_bfloat16* Ch1, __nv_bfloat16* Cl1,
              __nv_bfloat16* Ch2, __nv_bfloat16* Cl2,
              float sc0)
{
    extern __shared__ __align__(16) char dsm[];
    const int m0 = blockIdx.y * 256, n0 = blockIdx.x * 128;
    switch (blockIdx.z) {
        case 0: gemm_body(dsm, Ah0, Al0, Wh0, Wl0, b0, nullptr, Ch0, Cl0, 0, sc0, m0, n0); break;
        case 1: gemm_body(dsm, Ah1, Al1, Wh1, Wl1, b1, nullptr, Ch1, Cl1, 0, 1.0f, m0, n0); break;
        default: gemm_body(dsm, Ah2, Al2, Wh2, Wl2, b2, nullptr, Ch2, Cl2, 0, 1.0f, m0, n0); break;
    }
}

__global__ __launch_bounds__(512, 1)
void gemm_o(const __nv_bfloat16* Ah, const __nv_bfloat16* Al,
            const __nv_bfloat16* Wh, const __nv_bfloat16* Wl,
            const float* bias, float* Cf)
{
    extern __shared__ __align__(16) char dsm[];
    gemm_body(dsm, Ah, Al, Wh, Wl, bias, Cf, nullptr, nullptr, 2, 1.0f,
              blockIdx.y * 256, blockIdx.x * 128);
}

// ---------------------------------------------------------------------------
// Tensor-core flash attention (unchanged from R8).
// ---------------------------------------------------------------------------
#define AST 144
#define KVSTAGE (4 * 64 * AST)
#define MOFF (2 * KVSTAGE)
#define MSTAGE (64 * 80)
#define ATTN_SMEM (MOFF + 2 * MSTAGE)  // 83968

__global__ __launch_bounds__(128, 2)
void attn_mma(const __nv_bfloat16* __restrict__ qh_g, const __nv_bfloat16* __restrict__ ql_g,
              const __nv_bfloat16* __restrict__ kh_g, const __nv_bfloat16* __restrict__ kl_g,
              const __nv_bfloat16* __restrict__ vh_g, const __nv_bfloat16* __restrict__ vl_g,
              const unsigned char* __restrict__ maskp, const float* __restrict__ graph,
              __nv_bfloat16* __restrict__ ctxh, __nv_bfloat16* __restrict__ ctxl)
{
    extern __shared__ __align__(16) char dsm[];

    const int tid = threadIdx.x;
    const int w = tid >> 5, lane = tid & 31;
    const int g = lane >> 2, t = lane & 3;
    const int sub = lane >> 3;
    const int hh = blockIdx.y, b = blockIdx.z;
    const int q0 = blockIdx.x * 64;
    const bool lastH = (hh == Hn - 1);

    const size_t hoff = (size_t)((b * Hn + hh) * Sn) * DHn;
    const unsigned char* mbase = maskp + (size_t)(b * Sn) * Sn;
    const float* gbase = graph + (size_t)(b * Sn) * Sn;

    unsigned qh[4][4], ql[4][4];
    {
        const __nv_bfloat16* qb_h = qh_g + hoff + (size_t)(q0 + w * 16) * DHn;
        const __nv_bfloat16* qb_l = ql_g + hoff + (size_t)(q0 + w * 16) * DHn;
        #pragma unroll
        for (int kt = 0; kt < 4; kt++) {
            int c0 = kt * 16 + 2 * t;
            qh[kt][0] = *(const unsigned*)(qb_h + (size_t)g * DHn + c0);
            qh[kt][1] = *(const unsigned*)(qb_h + (size_t)(g + 8) * DHn + c0);
            qh[kt][2] = *(const unsigned*)(qb_h + (size_t)g * DHn + c0 + 8);
            qh[kt][3] = *(const unsigned*)(qb_h + (size_t)(g + 8) * DHn + c0 + 8);
            ql[kt][0] = *(const unsigned*)(qb_l + (size_t)g * DHn + c0);
            ql[kt][1] = *(const unsigned*)(qb_l + (size_t)(g + 8) * DHn + c0);
            ql[kt][2] = *(const unsigned*)(qb_l + (size_t)g * DHn + c0 + 8);
            ql[kt][3] = *(const unsigned*)(qb_l + (size_t)(g + 8) * DHn + c0 + 8);
        }
    }

    float O[8][4];
    #pragma unroll
    for (int nt = 0; nt < 8; nt++)
        #pragma unroll
        for (int e = 0; e < 4; e++) O[nt][e] = 0.f;
    float lA = 0.f, lB = 0.f;
    const int rA = w * 16 + g, rB = rA + 8;

    auto issue = [&](int kt16) {
        const int buf = kt16 & 1;
        char* st = dsm + buf * KVSTAGE;
        const int kt0 = kt16 * 64;
        #pragma unroll
        for (int i = 0; i < 4; i++) {
            int cc = i * 128 + tid;
            int r = cc >> 3, off = cc & 7;
            size_t gsrc = hoff + (size_t)(kt0 + r) * DHn + off * 8;
            CPA16(smem_u32(st + r * AST + off * 16),                kh_g + gsrc);
            CPA16(smem_u32(st + 64 * AST + r * AST + off * 16),     kl_g + gsrc);
            CPA16(smem_u32(st + 2 * 64 * AST + r * AST + off * 16), vh_g + gsrc);
            CPA16(smem_u32(st + 3 * 64 * AST + r * AST + off * 16), vl_g + gsrc);
        }
        char* ms = dsm + MOFF + buf * MSTAGE;
        #pragma unroll
        for (int i = 0; i < 2; i++) {
            int cc = i * 128 + tid;
            int r = cc >> 2, off = cc & 3;
            CPA16(smem_u32(ms + r * 80 + off * 16),
                  mbase + (size_t)(q0 + r) * Sn + kt0 + off * 16);
        }
    };

    issue(0);
    CPA_COMMIT();

    for (int kt16 = 0; kt16 < 16; kt16++) {
        if (kt16 + 1 < 16) { issue(kt16 + 1); CPA_COMMIT(); CPA_WAIT1(); }
        else               { CPA_WAIT0(); }
        __syncthreads();

        char* st = dsm + (kt16 & 1) * KVSTAGE;
        char* sKh = st;
        char* sKl = st + 64 * AST;
        char* sVh = st + 2 * 64 * AST;
        char* sVl = st + 3 * 64 * AST;
        unsigned char* Ms = (unsigned char*)(dsm + MOFF + (kt16 & 1) * MSTAGE);
        const int kt0 = kt16 * 64;

        float S[8][4];
        #pragma unroll
        for (int nt = 0; nt < 8; nt++)
            #pragma unroll
            for (int e = 0; e < 4; e++) S[nt][e] = 0.f;
        #pragma unroll
        for (int kt = 0; kt < 4; kt++) {
            unsigned th[4][4], tl[4][4];
            #pragma unroll
            for (int ntp = 0; ntp < 4; ntp++) {
                int r = (ntp * 2 + (sub >> 1)) * 8 + (lane & 7);
                int kb = kt * 32 + (sub & 1) * 16;
                ldsm4(th[ntp], smem_u32(sKh + r * AST + kb));
                ldsm4(tl[ntp], smem_u32(sKl + r * AST + kb));
            }
            #pragma unroll
            for (int ntp = 0; ntp < 4; ntp++) {
                mma16816(S[2 * ntp],     qh[kt], th[ntp]);
                mma16816(S[2 * ntp + 1], qh[kt], th[ntp] + 2);
            }
            #pragma unroll
            for (int ntp = 0; ntp < 4; ntp++) {
                mma16816(S[2 * ntp],     qh[kt], tl[ntp]);
                mma16816(S[2 * ntp + 1], qh[kt], tl[ntp] + 2);
            }
            #pragma unroll
            for (int ntp = 0; ntp < 4; ntp++) {
                mma16816(S[2 * ntp],     ql[kt], th[ntp]);
                mma16816(S[2 * ntp + 1], ql[kt], th[ntp] + 2);
            }
        }

        float2 gA[8], gB[8];
        if (lastH) {
            #pragma unroll
            for (int nt = 0; nt < 8; nt++) {
                int col = kt0 + nt * 8 + 2 * t;
                gA[nt] = *(const float2*)(gbase + (size_t)(q0 + rA) * Sn + col);
                gB[nt] = *(const float2*)(gbase + (size_t)(q0 + rB) * Sn + col);
            }
        }

        float la = 0.f, lb = 0.f;
        #pragma unroll
        for (int nt = 0; nt < 8; nt++) {
            const int col = nt * 8 + 2 * t;
            float p0 = exp2p(S[nt][0]);
            float p1 = exp2p(S[nt][1]);
            float p2 = exp2p(S[nt][2]);
            float p3 = exp2p(S[nt][3]);
            if (Ms[rA * 80 + col])     p0 = 0.f;
            if (Ms[rA * 80 + col + 1]) p1 = 0.f;
            if (Ms[rB * 80 + col])     p2 = 0.f;
            if (Ms[rB * 80 + col + 1]) p3 = 0.f;
            if (lastH) {
                p0 *= gA[nt].x; p1 *= gA[nt].y;
                p2 *= gB[nt].x; p3 *= gB[nt].y;
            }
            S[nt][0] = p0; S[nt][1] = p1; S[nt][2] = p2; S[nt][3] = p3;
            la += p0 + p1; lb += p2 + p3;
        }
        lA += la; lB += lb;

        #pragma unroll
        for (int kt = 0; kt < 4; kt++) {
            unsigned ph[4], pl[4];
            split_pack(S[2 * kt][0],     S[2 * kt][1],     ph[0], pl[0]);
            split_pack(S[2 * kt][2],     S[2 * kt][3],     ph[1], pl[1]);
            split_pack(S[2 * kt + 1][0], S[2 * kt + 1][1], ph[2], pl[2]);
            split_pack(S[2 * kt + 1][2], S[2 * kt + 1][3], ph[3], pl[3]);
            unsigned th[4][4], tl[4][4];
            #pragma unroll
            for (int ntp = 0; ntp < 4; ntp++) {
                int r = kt * 16 + (sub & 1) * 8 + (lane & 7);
                int cb = (2 * ntp + (sub >> 1)) * 16;
                ldsm4t(th[ntp], smem_u32(sVh + r * AST + cb));
                ldsm4t(tl[ntp], smem_u32(sVl + r * AST + cb));
            }
            #pragma unroll
            for (int ntp = 0; ntp < 4; ntp++) {
                mma16816(O[2 * ntp],     ph, th[ntp]);
                mma16816(O[2 * ntp + 1], ph, th[ntp] + 2);
            }
            #pragma unroll
            for (int ntp = 0; ntp < 4; ntp++) {
                mma16816(O[2 * ntp],     ph, tl[ntp]);
                mma16816(O[2 * ntp + 1], ph, tl[ntp] + 2);
            }
            #pragma unroll
            for (int ntp = 0; ntp < 4; ntp++) {
                mma16816(O[2 * ntp],     pl, th[ntp]);
                mma16816(O[2 * ntp + 1], pl, th[ntp] + 2);
            }
        }
        __syncthreads();
    }

    lA += __shfl_xor_sync(0xffffffff, lA, 1);
    lA += __shfl_xor_sync(0xffffffff, lA, 2);
    lB += __shfl_xor_sync(0xffffffff, lB, 1);
    lB += __shfl_xor_sync(0xffffffff, lB, 2);
    const float invA = 1.f / lA, invB = 1.f / lB;

    const int rowA = q0 + rA, rowB = q0 + rB;
    #pragma unroll
    for (int nt = 0; nt < 8; nt++) {
        const int col = hh * DHn + nt * 8 + 2 * t;
        unsigned hw, lw;
        split_pack(O[nt][0] * invA, O[nt][1] * invA, hw, lw);
        *(unsigned*)(ctxh + (size_t)(b * Sn + rowA) * Dn + col) = hw;
        *(unsigned*)(ctxl + (size_t)(b * Sn + rowA) * Dn + col) = lw;
        split_pack(O[nt][2] * invB, O[nt][3] * invB, hw, lw);
        *(unsigned*)(ctxh + (size_t)(b * Sn + rowB) * Dn + col) = hw;
        *(unsigned*)(ctxl + (size_t)(b * Sn + rowB) * Dn + col) = lw;
    }
}

// ---------------------------------------------------------------------------
// Launch
// ---------------------------------------------------------------------------
extern "C" void kernel_launch(void* const* d_in, const int* in_sizes, int n_in,
                              void* d_out, int out_size)
{
    const float* key   = (const float*)d_in[0];
    const float* value = (const float*)d_in[1];
    const float* query = (const float*)d_in[2];
    const int*   mask  = (const int*)d_in[3];
    const float* graph = (const float*)d_in[4];
    const float* Wq = (const float*)d_in[5];
    const float* bq = (const float*)d_in[6];
    const float* Wk = (const float*)d_in[7];
    const float* bk = (const float*)d_in[8];
    const float* Wv = (const float*)d_in[9];
    const float* bv = (const float*)d_in[10];
    const float* Wo = (const float*)d_in[11];
    const float* bo = (const float*)d_in[12];
    float* out = (float*)d_out;

    static int inited = 0;
    if (!inited) {
        cudaFuncSetAttribute(gemm_qkv, cudaFuncAttributeMaxDynamicSharedMemorySize, GEMM_SMEM);
        cudaFuncSetAttribute(gemm_o, cudaFuncAttributeMaxDynamicSharedMemorySize, GEMM_SMEM);
        cudaFuncSetAttribute(attn_mma, cudaFuncAttributeMaxDynamicSharedMemorySize, ATTN_SMEM);
        inited = 1;
    }

    #define SYM(p, s) void* p; cudaGetSymbolAddress(&p, s)
    SYM(iqh, gin_qh); SYM(iql, gin_ql);
    SYM(ikh, gin_kh); SYM(ikl, gin_kl);
    SYM(ivh, gin_vh); SYM(ivl, gin_vl);
    SYM(wqh, gWqh); SYM(wql, gWql);
    SYM(wkh, gWkh); SYM(wkl, gWkl);
    SYM(wvh, gWvh); SYM(wvl, gWvl);
    SYM(woh, gWoh); SYM(wol, gWol);
    SYM(pqh, g_qh); SYM(pql, g_ql);
    SYM(pkh, g_kh); SYM(pkl, g_kl);
    SYM(pvh, g_vh); SYM(pvl, g_vl);
    SYM(cxh, g_ctxh); SYM(cxl, g_ctxl);
    SYM(mpk, g_mask);
    #undef SYM

    typedef __nv_bfloat16 bf;
    const int nIn = Mn * Dn / 2, nW = Dn * Dn / 2;
    split_in3<<<dim3((nIn + 255) / 256, 3), 256>>>(
        query, key, value,
        (bf*)iqh, (bf*)iql, (bf*)ikh, (bf*)ikl, (bf*)ivh, (bf*)ivl, nIn);
    split_in4<<<dim3((nW + 255) / 256, 4), 256>>>(
        Wq, Wk, Wv, Wo,
        (bf*)wqh, (bf*)wql, (bf*)wkh, (bf*)wkl,
        (bf*)wvh, (bf*)wvl, (bf*)woh, (bf*)wol, nW);
    const int nM4 = Bn * Sn * Sn / 4;
    pack_mask<<<(nM4 + 255) / 256, 256>>>((const int4*)mask, (uchar4*)mpk, nM4);

    const float QSCALE = 0.125f * 1.4426950408889634f;   // fold log2e into Q
    dim3 qkvgrid(Dn / 128, Mn / 256, 3);   // (8, 32, 3)
    gemm_qkv<<<qkvgrid, 512, GEMM_SMEM>>>(
        (bf*)iqh, (bf*)iql, (bf*)ikh, (bf*)ikl, (bf*)ivh, (bf*)ivl,
        (bf*)wqh, (bf*)wql, (bf*)wkh, (bf*)wkl, (bf*)wvh, (bf*)wvl,
        bq, bk, bv,
        (bf*)pqh, (bf*)pql, (bf*)pkh, (bf*)pkl, (bf*)pvh, (bf*)pvl,
        QSCALE);

    attn_mma<<<dim3(Sn / 64, Hn, Bn), 128, ATTN_SMEM>>>(
        (const bf*)pqh, (const bf*)pql, (const bf*)pkh, (const bf*)pkl,
        (const bf*)pvh, (const bf*)pvl, (const unsigned char*)mpk, graph,
        (bf*)cxh, (bf*)cxl);

    gemm_o<<<dim3(Dn / 128, Mn / 256), 512, GEMM_SMEM>>>(
        (const bf*)cxh, (const bf*)cxl, (bf*)woh, (bf*)wol, bo, out);
}

// round 11
// speedup vs baseline: 1.5698x; 1.5698x over previous
#include <cuda_runtime.h>
#include <cuda_bf16.h>
#include <math_constants.h>

#define Bn  8
#define Sn  1024
#define Dn  1024
#define Hn  16
#define DHn 64
#define Mn  (Bn * Sn)   // 8192

// ---------------------------------------------------------------------------
// Device-global scratch
// ---------------------------------------------------------------------------
__device__ __nv_bfloat16 gin_qh[Mn * Dn], gin_ql[Mn * Dn];
__device__ __nv_bfloat16 gin_kh[Mn * Dn], gin_kl[Mn * Dn];
__device__ __nv_bfloat16 gin_vh[Mn * Dn], gin_vl[Mn * Dn];
__device__ __nv_bfloat16 gWqh[Dn * Dn], gWql[Dn * Dn];
__device__ __nv_bfloat16 gWkh[Dn * Dn], gWkl[Dn * Dn];
__device__ __nv_bfloat16 gWvh[Dn * Dn], gWvl[Dn * Dn];
__device__ __nv_bfloat16 gWoh[Dn * Dn], gWol[Dn * Dn];
__device__ __nv_bfloat16 g_qh[Mn * Dn], g_ql[Mn * Dn];   // [B,H,S,DH]
__device__ __nv_bfloat16 g_kh[Mn * Dn], g_kl[Mn * Dn];
__device__ __nv_bfloat16 g_vh[Mn * Dn], g_vl[Mn * Dn];
__device__ __nv_bfloat16 g_ctxh[Mn * Dn], g_ctxl[Mn * Dn]; // [B,S,D]
__device__ unsigned char g_mask[Bn * Sn * Sn];             // packed mask bytes

// ---------------------------------------------------------------------------
// helpers
// ---------------------------------------------------------------------------
__device__ __forceinline__ unsigned smem_u32(const void* p) {
    return (unsigned)__cvta_generic_to_shared(p);
}
__device__ __forceinline__ void mma16816(float* c, const unsigned* a, const unsigned* b) {
    asm volatile(
        "mma.sync.aligned.m16n8k16.row.col.f32.bf16.bf16.f32 "
        "{%0,%1,%2,%3},{%4,%5,%6,%7},{%8,%9},{%0,%1,%2,%3};\n"
        : "+f"(c[0]), "+f"(c[1]), "+f"(c[2]), "+f"(c[3])
        : "r"(a[0]), "r"(a[1]), "r"(a[2]), "r"(a[3]), "r"(b[0]), "r"(b[1]));
}
__device__ __forceinline__ void ldsm4(unsigned* r, unsigned addr) {
    asm volatile("ldmatrix.sync.aligned.m8n8.x4.shared.b16 {%0,%1,%2,%3},[%4];\n"
                 : "=r"(r[0]), "=r"(r[1]), "=r"(r[2]), "=r"(r[3]) : "r"(addr));
}
__device__ __forceinline__ void ldsm4t(unsigned* r, unsigned addr) {
    asm volatile("ldmatrix.sync.aligned.m8n8.x4.trans.shared.b16 {%0,%1,%2,%3},[%4];\n"
                 : "=r"(r[0]), "=r"(r[1]), "=r"(r[2]), "=r"(r[3]) : "r"(addr));
}
__device__ __forceinline__ void split_pack(float x, float y, unsigned& hi, unsigned& lo) {
    __nv_bfloat16 hx = __float2bfloat16(x);
    __nv_bfloat16 hy = __float2bfloat16(y);
    float rx = x - __bfloat162float(hx);
    float ry = y - __bfloat162float(hy);
    __nv_bfloat162 h; h.x = hx; h.y = hy;
    __nv_bfloat162 l; l.x = __float2bfloat16(rx); l.y = __float2bfloat16(ry);
    hi = *(unsigned*)&h;
    lo = *(unsigned*)&l;
}
// fast 2^y, FMA-only (no MUFU)
__device__ __forceinline__ float exp2p(float y) {
    y = fmaxf(fminf(y, 60.f), -60.f);
    float z = y + 12582912.f;              // 1.5*2^23
    int i = __float_as_int(z) << 23;
    float f = y - (z - 12582912.f);
    float p = 1.3333558e-3f;
    p = fmaf(p, f, 9.6181291e-3f);
    p = fmaf(p, f, 5.5504109e-2f);
    p = fmaf(p, f, 2.4022651e-1f);
    p = fmaf(p, f, 6.9314718e-1f);
    p = fmaf(p, f, 1.0f);
    return __int_as_float(__float_as_int(p) + i);
}
#define CPA16(smem, gmem) asm volatile("cp.async.cg.shared.global [%0], [%1], 16;\n" :: "r"(smem), "l"(gmem))
#define CPA_COMMIT()      asm volatile("cp.async.commit_group;\n")
#define CPA_WAIT0()       asm volatile("cp.async.wait_group 0;\n" ::: "memory")
#define CPA_WAIT1()       asm volatile("cp.async.wait_group 1;\n" ::: "memory")

// ---------------------------------------------------------------------------
// Pre-split kernels + mask pack
// ---------------------------------------------------------------------------
__device__ __forceinline__ void do_split(const float* src, __nv_bfloat16* hi,
                                         __nv_bfloat16* lo, int i) {
    float2 v = ((const float2*)src)[i];
    unsigned h, l;
    split_pack(v.x, v.y, h, l);
    ((unsigned*)hi)[i] = h;
    ((unsigned*)lo)[i] = l;
}
__global__ void split_in3(const float* __restrict__ s0, const float* __restrict__ s1,
                          const float* __restrict__ s2,
                          __nv_bfloat16* h0, __nv_bfloat16* l0,
                          __nv_bfloat16* h1, __nv_bfloat16* l1,
                          __nv_bfloat16* h2, __nv_bfloat16* l2, int n2)
{
    int i = blockIdx.x * blockDim.x + threadIdx.x;
    if (i >= n2) return;
    switch (blockIdx.y) {
        case 0: do_split(s0, h0, l0, i); break;
        case 1: do_split(s1, h1, l1, i); break;
        default: do_split(s2, h2, l2, i); break;
    }
}
__global__ void split_in4(const float* __restrict__ s0, const float* __restrict__ s1,
                          const float* __restrict__ s2, const float* __restrict__ s3,
                          __nv_bfloat16* h0, __nv_bfloat16* l0,
                          __nv_bfloat16* h1, __nv_bfloat16* l1,
                          __nv_bfloat16* h2, __nv_bfloat16* l2,
                          __nv_bfloat16* h3, __nv_bfloat16* l3, int n2)
{
    int i = blockIdx.x * blockDim.x + threadIdx.x;
    if (i >= n2) return;
    switch (blockIdx.y) {
        case 0: do_split(s0, h0, l0, i); break;
        case 1: do_split(s1, h1, l1, i); break;
        case 2: do_split(s2, h2, l2, i); break;
        default: do_split(s3, h3, l3, i); break;
    }
}
__global__ void pack_mask(const int4* __restrict__ m, uchar4* __restrict__ o, int n4)
{
    int i = blockIdx.x * blockDim.x + threadIdx.x;
    if (i < n4) {
        int4 v = m[i];
        o[i] = make_uchar4((unsigned char)(v.x != 0), (unsigned char)(v.y != 0),
                           (unsigned char)(v.z != 0), (unsigned char)(v.w != 0));
    }
}

// ---------------------------------------------------------------------------
// Split-bf16 (3x) GEMM body (EXACT R8 version: 128x128, BK=32, 256 thr,
// 2x4 warp grid, 2 CTAs/SM, cp.async double-buffered, term-outer order).
// ---------------------------------------------------------------------------
#define GST 80  // bytes per smem row (64B data + 16B pad)

__device__ __forceinline__
void gemm_body(char* dsm,
               const __nv_bfloat16* __restrict__ Ahi, const __nv_bfloat16* __restrict__ Alo,
               const __nv_bfloat16* __restrict__ Whi, const __nv_bfloat16* __restrict__ Wlo,
               const float* __restrict__ bias,
               float* __restrict__ Cf,
               __nv_bfloat16* __restrict__ Ch, __nv_bfloat16* __restrict__ Cl,
               int mode, float scale, int m0, int n0)
{
    const int tid = threadIdx.x;
    const int wid = tid >> 5, lane = tid & 31;
    const int wm = wid >> 2, wn = wid & 3;
    const int g = lane >> 2, t = lane & 3;
    const int sub = lane >> 3;

    float c[4][4][4];
    #pragma unroll
    for (int mt = 0; mt < 4; mt++)
        #pragma unroll
        for (int nt = 0; nt < 4; nt++)
            #pragma unroll
            for (int e = 0; e < 4; e++) c[mt][nt][e] = 0.f;

    auto issue = [&](int k0, int buf) {
        char* st = dsm + buf * 40960;
        #pragma unroll
        for (int i = 0; i < 2; i++) {
            int cc = i * 256 + tid;
            int r = cc >> 2, off = cc & 3;
            size_t ga = (size_t)(m0 + r) * Dn + k0 + off * 8;
            size_t gw = (size_t)(n0 + r) * Dn + k0 + off * 8;
            unsigned sa = smem_u32(st + r * GST + off * 16);
            CPA16(sa,         Ahi + ga);
            CPA16(sa + 10240, Alo + ga);
            CPA16(sa + 20480, Whi + gw);
            CPA16(sa + 30720, Wlo + gw);
        }
    };

    issue(0, 0);
    CPA_COMMIT();

    for (int it = 0; it < Dn / 32; it++) {
        CPA_WAIT0();
        __syncthreads();
        if (it + 1 < Dn / 32) { issue((it + 1) * 32, (it + 1) & 1); CPA_COMMIT(); }

        char* st = dsm + (it & 1) * 40960;
        char* sAh = st; char* sAl = st + 10240;
        char* sWh = st + 20480; char* sWl = st + 30720;

        #pragma unroll
        for (int kt = 0; kt < 2; kt++) {
            unsigned ah[4][4], al[4][4], bh[4][2], bl[4][2];
            #pragma unroll
            for (int mt = 0; mt < 4; mt++) {
                int r = wm * 64 + mt * 16 + (lane & 7) + (sub & 1) * 8;
                int kb = kt * 32 + (sub >> 1) * 16;
                ldsm4(ah[mt], smem_u32(sAh + r * GST + kb));
                ldsm4(al[mt], smem_u32(sAl + r * GST + kb));
            }
            #pragma unroll
            for (int ntp = 0; ntp < 2; ntp++) {
                int r = wn * 32 + (ntp * 2 + (sub >> 1)) * 8 + (lane & 7);
                int kb = kt * 32 + (sub & 1) * 16;
                unsigned tmp[4];
                ldsm4(tmp, smem_u32(sWh + r * GST + kb));
                bh[2 * ntp][0] = tmp[0]; bh[2 * ntp][1] = tmp[1];
                bh[2 * ntp + 1][0] = tmp[2]; bh[2 * ntp + 1][1] = tmp[3];
                ldsm4(tmp, smem_u32(sWl + r * GST + kb));
                bl[2 * ntp][0] = tmp[0]; bl[2 * ntp][1] = tmp[1];
                bl[2 * ntp + 1][0] = tmp[2]; bl[2 * ntp + 1][1] = tmp[3];
            }
            #pragma unroll
            for (int mt = 0; mt < 4; mt++)
                #pragma unroll
                for (int nt = 0; nt < 4; nt++)
                    mma16816(c[mt][nt], ah[mt], bh[nt]);
            #pragma unroll
            for (int mt = 0; mt < 4; mt++)
                #pragma unroll
                for (int nt = 0; nt < 4; nt++)
                    mma16816(c[mt][nt], ah[mt], bl[nt]);
            #pragma unroll
            for (int mt = 0; mt < 4; mt++)
                #pragma unroll
                for (int nt = 0; nt < 4; nt++)
                    mma16816(c[mt][nt], al[mt], bh[nt]);
        }
    }

    #pragma unroll
    for (int mt = 0; mt < 4; mt++) {
        #pragma unroll
        for (int nt = 0; nt < 4; nt++) {
            const int row = m0 + wm * 64 + mt * 16 + g;
            const int col = n0 + wn * 32 + nt * 8 + 2 * t;
            const float b0 = bias[col], b1 = bias[col + 1];
            #pragma unroll
            for (int half = 0; half < 2; half++) {
                const int r = row + half * 8;
                const float v0 = (c[mt][nt][half * 2 + 0] + b0) * scale;
                const float v1 = (c[mt][nt][half * 2 + 1] + b1) * scale;
                if (mode == 2) {
                    *(float2*)(Cf + (size_t)r * Dn + col) = make_float2(v0, v1);
                } else {
                    const int bb = r >> 10, s = r & 1023;
                    const int hh = col >> 6, d = col & 63;
                    size_t idx = (((size_t)(bb * Hn + hh) * Sn + s) * DHn) + d;
                    unsigned hw, lw;
                    split_pack(v0, v1, hw, lw);
                    *(unsigned*)(Ch + idx) = hw;
                    *(unsigned*)(Cl + idx) = lw;
                }
            }
        }
    }
}

// fused Q/K/V projections: blockIdx.z selects the matmul
__global__ __launch_bounds__(256)
void gemm_qkv(const __nv_bfloat16* Ah0, const __nv_bfloat16* Al0,
              const __nv_bfloat16* Ah1, const __nv_bfloat16* Al1,
              const __nv_bfloat16* Ah2, const __nv_bfloat16* Al2,
              const __nv_bfloat16* Wh0, const __nv_bfloat16* Wl0,
              const __nv_bfloat16* Wh1, const __nv_bfloat16* Wl1,
              const __nv_bfloat16* Wh2, const __nv_bfloat16* Wl2,
              const float* b0, const float* b1, const float* b2,
              __nv_bfloat16* Ch0, __nv_bfloat16* Cl0,
              __nv_bfloat16* Ch1, __nv_bfloat16* Cl1,
              __nv_bfloat16* Ch2, __nv_bfloat16* Cl2,
              float sc0)
{
    extern __shared__ __align__(16) char dsm[];
    const int m0 = blockIdx.y * 128, n0 = blockIdx.x * 128;
    switch (blockIdx.z) {
        case 0: gemm_body(dsm, Ah0, Al0, Wh0, Wl0, b0, nullptr, Ch0, Cl0, 0, sc0, m0, n0); break;
        case 1: gemm_body(dsm, Ah1, Al1, Wh1, Wl1, b1, nullptr, Ch1, Cl1, 0, 1.0f, m0, n0); break;
        default: gemm_body(dsm, Ah2, Al2, Wh2, Wl2, b2, nullptr, Ch2, Cl2, 0, 1.0f, m0, n0); break;
    }
}

__global__ __launch_bounds__(256)
void gemm_o(const __nv_bfloat16* Ah, const __nv_bfloat16* Al,
            const __nv_bfloat16* Wh, const __nv_bfloat16* Wl,
            const float* bias, float* Cf)
{
    extern __shared__ __align__(16) char dsm[];
    gemm_body(dsm, Ah, Al, Wh, Wl, bias, Cf, nullptr, nullptr, 2, 1.0f,
              blockIdx.y * 128, blockIdx.x * 128);
}

// ---------------------------------------------------------------------------
// Tensor-core flash attention: 4 warps x 32 q-rows (two 16-row groups/warp).
// K/V fragments loaded once per kt, reused by both groups -> half the smem
// crossbar traffic per FLOP vs R8. MUFU-free softmax; double-buffered
// K/V/mask via cp.async; graph applied via inline loads (last head only).
// CTA covers 128 q-rows; grid (S/128, H, B).
// ---------------------------------------------------------------------------
#define AST 144                 // bytes per K/V smem row (128B data + 16B pad)
#define KVSTAGE (4 * 64 * AST)  // 36864 per stage (Kh,Kl,Vh,Vl)
#define MOFF (2 * KVSTAGE)      // 73728
#define MSTAGE (128 * 80)       // 10240 per stage
#define ATTN_SMEM (MOFF + 2 * MSTAGE)  // 94208

__global__ __launch_bounds__(128, 2)
void attn_mma(const __nv_bfloat16* __restrict__ qh_g, const __nv_bfloat16* __restrict__ ql_g,
              const __nv_bfloat16* __restrict__ kh_g, const __nv_bfloat16* __restrict__ kl_g,
              const __nv_bfloat16* __restrict__ vh_g, const __nv_bfloat16* __restrict__ vl_g,
              const unsigned char* __restrict__ maskp, const float* __restrict__ graph,
              __nv_bfloat16* __restrict__ ctxh, __nv_bfloat16* __restrict__ ctxl)
{
    extern __shared__ __align__(16) char dsm[];

    const int tid = threadIdx.x;
    const int w = tid >> 5, lane = tid & 31;
    const int g = lane >> 2, t = lane & 3;
    const int sub = lane >> 3;
    const int hh = blockIdx.y, b = blockIdx.z;
    const int q0 = blockIdx.x * 128;
    const bool lastH = (hh == Hn - 1);

    const size_t hoff = (size_t)((b * Hn + hh) * Sn) * DHn;
    const unsigned char* mbase = maskp + (size_t)(b * Sn) * Sn;
    const float* gbase = graph + (size_t)(b * Sn) * Sn;

    // Q fragments for two 16-row groups
    unsigned qh[2][4][4], ql[2][4][4];
    #pragma unroll
    for (int grp = 0; grp < 2; grp++) {
        const __nv_bfloat16* qb_h = qh_g + hoff + (size_t)(q0 + w * 32 + grp * 16) * DHn;
        const __nv_bfloat16* qb_l = ql_g + hoff + (size_t)(q0 + w * 32 + grp * 16) * DHn;
        #pragma unroll
        for (int kt = 0; kt < 4; kt++) {
            int c0 = kt * 16 + 2 * t;
            qh[grp][kt][0] = *(const unsigned*)(qb_h + (size_t)g * DHn + c0);
            qh[grp][kt][1] = *(const unsigned*)(qb_h + (size_t)(g + 8) * DHn + c0);
            qh[grp][kt][2] = *(const unsigned*)(qb_h + (size_t)g * DHn + c0 + 8);
            qh[grp][kt][3] = *(const unsigned*)(qb_h + (size_t)(g + 8) * DHn + c0 + 8);
            ql[grp][kt][0] = *(const unsigned*)(qb_l + (size_t)g * DHn + c0);
            ql[grp][kt][1] = *(const unsigned*)(qb_l + (size_t)(g + 8) * DHn + c0);
            ql[grp][kt][2] = *(const unsigned*)(qb_l + (size_t)g * DHn + c0 + 8);
            ql[grp][kt][3] = *(const unsigned*)(qb_l + (size_t)(g + 8) * DHn + c0 + 8);
        }
    }

    float O[2][8][4];
    #pragma unroll
    for (int grp = 0; grp < 2; grp++)
        #pragma unroll
        for (int nt = 0; nt < 8; nt++)
            #pragma unroll
            for (int e = 0; e < 4; e++) O[grp][nt][e] = 0.f;
    float lA[2] = {0.f, 0.f}, lB[2] = {0.f, 0.f};

    auto issue = [&](int kt16) {
        const int buf = kt16 & 1;
        char* st = dsm + buf * KVSTAGE;
        const int kt0 = kt16 * 64;
        #pragma unroll
        for (int i = 0; i < 4; i++) {
            int cc = i * 128 + tid;
            int r = cc >> 3, off = cc & 7;
            size_t gsrc = hoff + (size_t)(kt0 + r) * DHn + off * 8;
            CPA16(smem_u32(st + r * AST + off * 16),                kh_g + gsrc);
            CPA16(smem_u32(st + 64 * AST + r * AST + off * 16),     kl_g + gsrc);
            CPA16(smem_u32(st + 2 * 64 * AST + r * AST + off * 16), vh_g + gsrc);
            CPA16(smem_u32(st + 3 * 64 * AST + r * AST + off * 16), vl_g + gsrc);
        }
        char* ms = dsm + MOFF + buf * MSTAGE;
        #pragma unroll
        for (int i = 0; i < 4; i++) {
            int cc = i * 128 + tid;          // 0..511
            int r = cc >> 2, off = cc & 3;   // 128 rows x 4 chunks
            CPA16(smem_u32(ms + r * 80 + off * 16),
                  mbase + (size_t)(q0 + r) * Sn + kt0 + off * 16);
        }
    };

    issue(0);
    CPA_COMMIT();

    for (int kt16 = 0; kt16 < 16; kt16++) {
        if (kt16 + 1 < 16) { issue(kt16 + 1); CPA_COMMIT(); CPA_WAIT1(); }
        else               { CPA_WAIT0(); }
        __syncthreads();

        char* st = dsm + (kt16 & 1) * KVSTAGE;
        char* sKh = st;
        char* sKl = st + 64 * AST;
        char* sVh = st + 2 * 64 * AST;
        char* sVl = st + 3 * 64 * AST;
        unsigned char* Ms = (unsigned char*)(dsm + MOFF + (kt16 & 1) * MSTAGE);
        const int kt0 = kt16 * 64;

        // S = Q K^T for both groups; K frags loaded ONCE per kt
        float S[2][8][4];
        #pragma unroll
        for (int grp = 0; grp < 2; grp++)
            #pragma unroll
            for (int nt = 0; nt < 8; nt++)
                #pragma unroll
                for (int e = 0; e < 4; e++) S[grp][nt][e] = 0.f;
        #pragma unroll
        for (int kt = 0; kt < 4; kt++) {
            unsigned th[4][4], tl[4][4];
            #pragma unroll
            for (int ntp = 0; ntp < 4; ntp++) {
                int r = (ntp * 2 + (sub >> 1)) * 8 + (lane & 7);
                int kb = kt * 32 + (sub & 1) * 16;
                ldsm4(th[ntp], smem_u32(sKh + r * AST + kb));
                ldsm4(tl[ntp], smem_u32(sKl + r * AST + kb));
            }
            #pragma unroll
            for (int grp = 0; grp < 2; grp++) {
                #pragma unroll
                for (int ntp = 0; ntp < 4; ntp++) {
                    mma16816(S[grp][2 * ntp],     qh[grp][kt], th[ntp]);
                    mma16816(S[grp][2 * ntp + 1], qh[grp][kt], th[ntp] + 2);
                }
                #pragma unroll
                for (int ntp = 0; ntp < 4; ntp++) {
                    mma16816(S[grp][2 * ntp],     qh[grp][kt], tl[ntp]);
                    mma16816(S[grp][2 * ntp + 1], qh[grp][kt], tl[ntp] + 2);
                }
                #pragma unroll
                for (int ntp = 0; ntp < 4; ntp++) {
                    mma16816(S[grp][2 * ntp],     ql[grp][kt], th[ntp]);
                    mma16816(S[grp][2 * ntp + 1], ql[grp][kt], th[ntp] + 2);
                }
            }
        }

        // softmax per group: p = 2^s, mask -> 0, graph inline (last head)
        #pragma unroll
        for (int grp = 0; grp < 2; grp++) {
            const int ra = w * 32 + grp * 16 + g, rb = ra + 8;
            float la = 0.f, lb = 0.f;
            #pragma unroll
            for (int nt = 0; nt < 8; nt++) {
                const int col = nt * 8 + 2 * t;
                float p0 = exp2p(S[grp][nt][0]);
                float p1 = exp2p(S[grp][nt][1]);
                float p2 = exp2p(S[grp][nt][2]);
                float p3 = exp2p(S[grp][nt][3]);
                if (Ms[ra * 80 + col])     p0 = 0.f;
                if (Ms[ra * 80 + col + 1]) p1 = 0.f;
                if (Ms[rb * 80 + col])     p2 = 0.f;
                if (Ms[rb * 80 + col + 1]) p3 = 0.f;
                if (lastH) {
                    float2 ga = *(const float2*)(gbase + (size_t)(q0 + ra) * Sn + kt0 + col);
                    float2 gb = *(const float2*)(gbase + (size_t)(q0 + rb) * Sn + kt0 + col);
                    p0 *= ga.x; p1 *= ga.y;
                    p2 *= gb.x; p3 *= gb.y;
                }
                S[grp][nt][0] = p0; S[grp][nt][1] = p1;
                S[grp][nt][2] = p2; S[grp][nt][3] = p3;
                la += p0 + p1; lb += p2 + p3;
            }
            lA[grp] += la; lB[grp] += lb;
        }

        // O += P V for both groups; V frags loaded ONCE per kt
        #pragma unroll
        for (int kt = 0; kt < 4; kt++) {
            unsigned th[4][4], tl[4][4];
            #pragma unroll
            for (int ntp = 0; ntp < 4; ntp++) {
                int r = kt * 16 + (sub & 1) * 8 + (lane & 7);
                int cb = (2 * ntp + (sub >> 1)) * 16;
                ldsm4t(th[ntp], smem_u32(sVh + r * AST + cb));
                ldsm4t(tl[ntp], smem_u32(sVl + r * AST + cb));
            }
            #pragma unroll
            for (int grp = 0; grp < 2; grp++) {
                unsigned ph[4], pl[4];
                split_pack(S[grp][2 * kt][0],     S[grp][2 * kt][1],     ph[0], pl[0]);
                split_pack(S[grp][2 * kt][2],     S[grp][2 * kt][3],     ph[1], pl[1]);
                split_pack(S[grp][2 * kt + 1][0], S[grp][2 * kt + 1][1], ph[2], pl[2]);
                split_pack(S[grp][2 * kt + 1][2], S[grp][2 * kt + 1][3], ph[3], pl[3]);
                #pragma unroll
                for (int ntp = 0; ntp < 4; ntp++) {
                    mma16816(O[grp][2 * ntp],     ph, th[ntp]);
                    mma16816(O[grp][2 * ntp + 1], ph, th[ntp] + 2);
                }
                #pragma unroll
                for (int ntp = 0; ntp < 4; ntp++) {
                    mma16816(O[grp][2 * ntp],     ph, tl[ntp]);
                    mma16816(O[grp][2 * ntp + 1], ph, tl[ntp] + 2);
                }
                #pragma unroll
                for (int ntp = 0; ntp < 4; ntp++) {
                    mma16816(O[grp][2 * ntp],     pl, th[ntp]);
                    mma16816(O[grp][2 * ntp + 1], pl, th[ntp] + 2);
                }
            }
        }
        __syncthreads();
    }

    // finalize per group
    #pragma unroll
    for (int grp = 0; grp < 2; grp++) {
        float la = lA[grp], lb = lB[grp];
        la += __shfl_xor_sync(0xffffffff, la, 1);
        la += __shfl_xor_sync(0xffffffff, la, 2);
        lb += __shfl_xor_sync(0xffffffff, lb, 1);
        lb += __shfl_xor_sync(0xffffffff, lb, 2);
        const float invA = 1.f / la, invB = 1.f / lb;

        const int rowA = q0 + w * 32 + grp * 16 + g, rowB = rowA + 8;
        #pragma unroll
        for (int nt = 0; nt < 8; nt++) {
            const int col = hh * DHn + nt * 8 + 2 * t;
            unsigned hw, lw;
            split_pack(O[grp][nt][0] * invA, O[grp][nt][1] * invA, hw, lw);
            *(unsigned*)(ctxh + (size_t)(b * Sn + rowA) * Dn + col) = hw;
            *(unsigned*)(ctxl + (size_t)(b * Sn + rowA) * Dn + col) = lw;
            split_pack(O[grp][nt][2] * invB, O[grp][nt][3] * invB, hw, lw);
            *(unsigned*)(ctxh + (size_t)(b * Sn + rowB) * Dn + col) = hw;
            *(unsigned*)(ctxl + (size_t)(b * Sn + rowB) * Dn + col) = lw;
        }
    }
}

// ---------------------------------------------------------------------------
// Launch
// ---------------------------------------------------------------------------
extern "C" void kernel_launch(void* const* d_in, const int* in_sizes, int n_in,
                              void* d_out, int out_size)
{
    const float* key   = (const float*)d_in[0];
    const float* value = (const float*)d_in[1];
    const float* query = (const float*)d_in[2];
    const int*   mask  = (const int*)d_in[3];
    const float* graph = (const float*)d_in[4];
    const float* Wq = (const float*)d_in[5];
    const float* bq = (const float*)d_in[6];
    const float* Wk = (const float*)d_in[7];
    const float* bk = (const float*)d_in[8];
    const float* Wv = (const float*)d_in[9];
    const float* bv = (const float*)d_in[10];
    const float* Wo = (const float*)d_in[11];
    const float* bo = (const float*)d_in[12];
    float* out = (float*)d_out;

    static int inited = 0;
    if (!inited) {
        cudaFuncSetAttribute(gemm_qkv, cudaFuncAttributeMaxDynamicSharedMemorySize, 81920);
        cudaFuncSetAttribute(gemm_o, cudaFuncAttributeMaxDynamicSharedMemorySize, 81920);
        cudaFuncSetAttribute(attn_mma, cudaFuncAttributeMaxDynamicSharedMemorySize, ATTN_SMEM);
        inited = 1;
    }

    #define SYM(p, s) void* p; cudaGetSymbolAddress(&p, s)
    SYM(iqh, gin_qh); SYM(iql, gin_ql);
    SYM(ikh, gin_kh); SYM(ikl, gin_kl);
    SYM(ivh, gin_vh); SYM(ivl, gin_vl);
    SYM(wqh, gWqh); SYM(wql, gWql);
    SYM(wkh, gWkh); SYM(wkl, gWkl);
    SYM(wvh, gWvh); SYM(wvl, gWvl);
    SYM(woh, gWoh); SYM(wol, gWol);
    SYM(pqh, g_qh); SYM(pql, g_ql);
    SYM(pkh, g_kh); SYM(pkl, g_kl);
    SYM(pvh, g_vh); SYM(pvl, g_vl);
    SYM(cxh, g_ctxh); SYM(cxl, g_ctxl);
    SYM(mpk, g_mask);
    #undef SYM

    typedef __nv_bfloat16 bf;
    const int nIn = Mn * Dn / 2, nW = Dn * Dn / 2;
    split_in3<<<dim3((nIn + 255) / 256, 3), 256>>>(
        query, key, value,
        (bf*)iqh, (bf*)iql, (bf*)ikh, (bf*)ikl, (bf*)ivh, (bf*)ivl, nIn);
    split_in4<<<dim3((nW + 255) / 256, 4), 256>>>(
        Wq, Wk, Wv, Wo,
        (bf*)wqh, (bf*)wql, (bf*)wkh, (bf*)wkl,
        (bf*)wvh, (bf*)wvl, (bf*)woh, (bf*)wol, nW);
    const int nM4 = Bn * Sn * Sn / 4;
    pack_mask<<<(nM4 + 255) / 256, 256>>>((const int4*)mask, (uchar4*)mpk, nM4);

    const float QSCALE = 0.125f * 1.4426950408889634f;   // fold log2e into Q
    dim3 qkvgrid(Dn / 128, Mn / 128, 3);   // (8, 64, 3)
    gemm_qkv<<<qkvgrid, 256, 81920>>>(
        (bf*)iqh, (bf*)iql, (bf*)ikh, (bf*)ikl, (bf*)ivh, (bf*)ivl,
        (bf*)wqh, (bf*)wql, (bf*)wkh, (bf*)wkl, (bf*)wvh, (bf*)wvl,
        bq, bk, bv,
        (bf*)pqh, (bf*)pql, (bf*)pkh, (bf*)pkl, (bf*)pvh, (bf*)pvl,
        QSCALE);

    attn_mma<<<dim3(Sn / 128, Hn, Bn), 128, ATTN_SMEM>>>(
        (const bf*)pqh, (const bf*)pql, (const bf*)pkh, (const bf*)pkl,
        (const bf*)pvh, (const bf*)pvl, (const unsigned char*)mpk, graph,
        (bf*)cxh, (bf*)cxl);

    gemm_o<<<dim3(Dn / 128, Mn / 128), 256, 81920>>>(
        (const bf*)cxh, (const bf*)cxl, (bf*)woh, (bf*)wol, bo, out);
}

// round 13
// speedup vs baseline: 1.5969x; 1.0173x over previous
#include <cuda_runtime.h>
#include <cuda_bf16.h>
#include <math_constants.h>

#define Bn  8
#define Sn  1024
#define Dn  1024
#define Hn  16
#define DHn 64
#define Mn  (Bn * Sn)   // 8192

// ---------------------------------------------------------------------------
// Device-global scratch
// ---------------------------------------------------------------------------
__device__ __nv_bfloat16 gin_qh[Mn * Dn], gin_ql[Mn * Dn];
__device__ __nv_bfloat16 gin_kh[Mn * Dn], gin_kl[Mn * Dn];
__device__ __nv_bfloat16 gin_vh[Mn * Dn], gin_vl[Mn * Dn];
__device__ __nv_bfloat16 gWqh[Dn * Dn], gWql[Dn * Dn];
__device__ __nv_bfloat16 gWkh[Dn * Dn], gWkl[Dn * Dn];
__device__ __nv_bfloat16 gWvh[Dn * Dn], gWvl[Dn * Dn];
__device__ __nv_bfloat16 gWoh[Dn * Dn], gWol[Dn * Dn];
__device__ __nv_bfloat16 g_qh[Mn * Dn], g_ql[Mn * Dn];   // [B,H,S,DH]
__device__ __nv_bfloat16 g_kh[Mn * Dn], g_kl[Mn * Dn];
__device__ __nv_bfloat16 g_vh[Mn * Dn], g_vl[Mn * Dn];
__device__ __nv_bfloat16 g_ctxh[Mn * Dn], g_ctxl[Mn * Dn]; // [B,S,D]
__device__ unsigned char g_mask[Bn * Sn * Sn];             // packed mask bytes

// ---------------------------------------------------------------------------
// helpers
// ---------------------------------------------------------------------------
__device__ __forceinline__ unsigned smem_u32(const void* p) {
    return (unsigned)__cvta_generic_to_shared(p);
}
__device__ __forceinline__ void mma16816(float* c, const unsigned* a, const unsigned* b) {
    asm volatile(
        "mma.sync.aligned.m16n8k16.row.col.f32.bf16.bf16.f32 "
        "{%0,%1,%2,%3},{%4,%5,%6,%7},{%8,%9},{%0,%1,%2,%3};\n"
        : "+f"(c[0]), "+f"(c[1]), "+f"(c[2]), "+f"(c[3])
        : "r"(a[0]), "r"(a[1]), "r"(a[2]), "r"(a[3]), "r"(b[0]), "r"(b[1]));
}
__device__ __forceinline__ void ldsm4(unsigned* r, unsigned addr) {
    asm volatile("ldmatrix.sync.aligned.m8n8.x4.shared.b16 {%0,%1,%2,%3},[%4];\n"
                 : "=r"(r[0]), "=r"(r[1]), "=r"(r[2]), "=r"(r[3]) : "r"(addr));
}
__device__ __forceinline__ void ldsm4t(unsigned* r, unsigned addr) {
    asm volatile("ldmatrix.sync.aligned.m8n8.x4.trans.shared.b16 {%0,%1,%2,%3},[%4];\n"
                 : "=r"(r[0]), "=r"(r[1]), "=r"(r[2]), "=r"(r[3]) : "r"(addr));
}
__device__ __forceinline__ void split_pack(float x, float y, unsigned& hi, unsigned& lo) {
    __nv_bfloat16 hx = __float2bfloat16(x);
    __nv_bfloat16 hy = __float2bfloat16(y);
    float rx = x - __bfloat162float(hx);
    float ry = y - __bfloat162float(hy);
    __nv_bfloat162 h; h.x = hx; h.y = hy;
    __nv_bfloat162 l; l.x = __float2bfloat16(rx); l.y = __float2bfloat16(ry);
    hi = *(unsigned*)&h;
    lo = *(unsigned*)&l;
}
// fast 2^y, FMA-only (no MUFU)
__device__ __forceinline__ float exp2p(float y) {
    y = fmaxf(fminf(y, 60.f), -60.f);
    float z = y + 12582912.f;              // 1.5*2^23
    int i = __float_as_int(z) << 23;
    float f = y - (z - 12582912.f);
    float p = 1.3333558e-3f;
    p = fmaf(p, f, 9.6181291e-3f);
    p = fmaf(p, f, 5.5504109e-2f);
    p = fmaf(p, f, 2.4022651e-1f);
    p = fmaf(p, f, 6.9314718e-1f);
    p = fmaf(p, f, 1.0f);
    return __int_as_float(__float_as_int(p) + i);
}
#define CPA16(smem, gmem) asm volatile("cp.async.cg.shared.global [%0], [%1], 16;\n" :: "r"(smem), "l"(gmem))
#define CPA_COMMIT()      asm volatile("cp.async.commit_group;\n")
#define CPA_WAIT0()       asm volatile("cp.async.wait_group 0;\n" ::: "memory")
#define CPA_WAIT1()       asm volatile("cp.async.wait_group 1;\n" ::: "memory")

// ---------------------------------------------------------------------------
// Pre-split kernels + mask pack
// ---------------------------------------------------------------------------
__device__ __forceinline__ void do_split(const float* src, __nv_bfloat16* hi,
                                         __nv_bfloat16* lo, int i) {
    float2 v = ((const float2*)src)[i];
    unsigned h, l;
    split_pack(v.x, v.y, h, l);
    ((unsigned*)hi)[i] = h;
    ((unsigned*)lo)[i] = l;
}
__global__ void split_in3(const float* __restrict__ s0, const float* __restrict__ s1,
                          const float* __restrict__ s2,
                          __nv_bfloat16* h0, __nv_bfloat16* l0,
                          __nv_bfloat16* h1, __nv_bfloat16* l1,
                          __nv_bfloat16* h2, __nv_bfloat16* l2, int n2)
{
    int i = blockIdx.x * blockDim.x + threadIdx.x;
    if (i >= n2) return;
    switch (blockIdx.y) {
        case 0: do_split(s0, h0, l0, i); break;
        case 1: do_split(s1, h1, l1, i); break;
        default: do_split(s2, h2, l2, i); break;
    }
}
__global__ void split_in1(const float* __restrict__ s0,
                          __nv_bfloat16* h0, __nv_bfloat16* l0, int n2)
{
    int i = blockIdx.x * blockDim.x + threadIdx.x;
    if (i < n2) do_split(s0, h0, l0, i);
}
__global__ void pack_mask(const int4* __restrict__ m, uchar4* __restrict__ o, int n4)
{
    int i = blockIdx.x * blockDim.x + threadIdx.x;
    if (i < n4) {
        int4 v = m[i];
        o[i] = make_uchar4((unsigned char)(v.x != 0), (unsigned char)(v.y != 0),
                           (unsigned char)(v.z != 0), (unsigned char)(v.w != 0));
    }
}

// ---------------------------------------------------------------------------
// Split-bf16 (3x) GEMM body (EXACT R8 version: 128x128, BK=32, 256 thr,
// 2x4 warp grid, 2 CTAs/SM, cp.async double-buffered, term-outer order).
// ---------------------------------------------------------------------------
#define GST 80  // bytes per smem row (64B data + 16B pad)

__device__ __forceinline__
void gemm_body(char* dsm,
               const __nv_bfloat16* __restrict__ Ahi, const __nv_bfloat16* __restrict__ Alo,
               const __nv_bfloat16* __restrict__ Whi, const __nv_bfloat16* __restrict__ Wlo,
               const float* __restrict__ bias,
               float* __restrict__ Cf,
               __nv_bfloat16* __restrict__ Ch, __nv_bfloat16* __restrict__ Cl,
               int mode, float scale, int m0, int n0)
{
    const int tid = threadIdx.x;
    const int wid = tid >> 5, lane = tid & 31;
    const int wm = wid >> 2, wn = wid & 3;
    const int g = lane >> 2, t = lane & 3;
    const int sub = lane >> 3;

    float c[4][4][4];
    #pragma unroll
    for (int mt = 0; mt < 4; mt++)
        #pragma unroll
        for (int nt = 0; nt < 4; nt++)
            #pragma unroll
            for (int e = 0; e < 4; e++) c[mt][nt][e] = 0.f;

    auto issue = [&](int k0, int buf) {
        char* st = dsm + buf * 40960;
        #pragma unroll
        for (int i = 0; i < 2; i++) {
            int cc = i * 256 + tid;
            int r = cc >> 2, off = cc & 3;
            size_t ga = (size_t)(m0 + r) * Dn + k0 + off * 8;
            size_t gw = (size_t)(n0 + r) * Dn + k0 + off * 8;
            unsigned sa = smem_u32(st + r * GST + off * 16);
            CPA16(sa,         Ahi + ga);
            CPA16(sa + 10240, Alo + ga);
            CPA16(sa + 20480, Whi + gw);
            CPA16(sa + 30720, Wlo + gw);
        }
    };

    issue(0, 0);
    CPA_COMMIT();

    for (int it = 0; it < Dn / 32; it++) {
        CPA_WAIT0();
        __syncthreads();
        if (it + 1 < Dn / 32) { issue((it + 1) * 32, (it + 1) & 1); CPA_COMMIT(); }

        char* st = dsm + (it & 1) * 40960;
        char* sAh = st; char* sAl = st + 10240;
        char* sWh = st + 20480; char* sWl = st + 30720;

        #pragma unroll
        for (int kt = 0; kt < 2; kt++) {
            unsigned ah[4][4], al[4][4], bh[4][2], bl[4][2];
            #pragma unroll
            for (int mt = 0; mt < 4; mt++) {
                int r = wm * 64 + mt * 16 + (lane & 7) + (sub & 1) * 8;
                int kb = kt * 32 + (sub >> 1) * 16;
                ldsm4(ah[mt], smem_u32(sAh + r * GST + kb));
                ldsm4(al[mt], smem_u32(sAl + r * GST + kb));
            }
            #pragma unroll
            for (int ntp = 0; ntp < 2; ntp++) {
                int r = wn * 32 + (ntp * 2 + (sub >> 1)) * 8 + (lane & 7);
                int kb = kt * 32 + (sub & 1) * 16;
                unsigned tmp[4];
                ldsm4(tmp, smem_u32(sWh + r * GST + kb));
                bh[2 * ntp][0] = tmp[0]; bh[2 * ntp][1] = tmp[1];
                bh[2 * ntp + 1][0] = tmp[2]; bh[2 * ntp + 1][1] = tmp[3];
                ldsm4(tmp, smem_u32(sWl + r * GST + kb));
                bl[2 * ntp][0] = tmp[0]; bl[2 * ntp][1] = tmp[1];
                bl[2 * ntp + 1][0] = tmp[2]; bl[2 * ntp + 1][1] = tmp[3];
            }
            #pragma unroll
            for (int mt = 0; mt < 4; mt++)
                #pragma unroll
                for (int nt = 0; nt < 4; nt++)
                    mma16816(c[mt][nt], ah[mt], bh[nt]);
            #pragma unroll
            for (int mt = 0; mt < 4; mt++)
                #pragma unroll
                for (int nt = 0; nt < 4; nt++)
                    mma16816(c[mt][nt], ah[mt], bl[nt]);
            #pragma unroll
            for (int mt = 0; mt < 4; mt++)
                #pragma unroll
                for (int nt = 0; nt < 4; nt++)
                    mma16816(c[mt][nt], al[mt], bh[nt]);
        }
    }

    #pragma unroll
    for (int mt = 0; mt < 4; mt++) {
        #pragma unroll
        for (int nt = 0; nt < 4; nt++) {
            const int row = m0 + wm * 64 + mt * 16 + g;
            const int col = n0 + wn * 32 + nt * 8 + 2 * t;
            const float b0 = bias[col], b1 = bias[col + 1];
            #pragma unroll
            for (int half = 0; half < 2; half++) {
                const int r = row + half * 8;
                const float v0 = (c[mt][nt][half * 2 + 0] + b0) * scale;
                const float v1 = (c[mt][nt][half * 2 + 1] + b1) * scale;
                if (mode == 2) {
                    *(float2*)(Cf + (size_t)r * Dn + col) = make_float2(v0, v1);
                } else {
                    const int bb = r >> 10, s = r & 1023;
                    const int hh = col >> 6, d = col & 63;
                    size_t idx = (((size_t)(bb * Hn + hh) * Sn + s) * DHn) + d;
                    unsigned hw, lw;
                    split_pack(v0, v1, hw, lw);
                    *(unsigned*)(Ch + idx) = hw;
                    *(unsigned*)(Cl + idx) = lw;
                }
            }
        }
    }
}

// fused Q/K/V projections: blockIdx.z selects the matmul
__global__ __launch_bounds__(256)
void gemm_qkv(const __nv_bfloat16* Ah0, const __nv_bfloat16* Al0,
              const __nv_bfloat16* Ah1, const __nv_bfloat16* Al1,
              const __nv_bfloat16* Ah2, const __nv_bfloat16* Al2,
              const __nv_bfloat16* Wh0, const __nv_bfloat16* Wl0,
              const __nv_bfloat16* Wh1, const __nv_bfloat16* Wl1,
              const __nv_bfloat16* Wh2, const __nv_bfloat16* Wl2,
              const float* b0, const float* b1, const float* b2,
              __nv_bfloat16* Ch0, __nv_bfloat16* Cl0,
              __nv_bfloat16* Ch1, __nv_bfloat16* Cl1,
              __nv_bfloat16* Ch2, __nv_bfloat16* Cl2,
              float sc0)
{
    extern __shared__ __align__(16) char dsm[];
    const int m0 = blockIdx.y * 128, n0 = blockIdx.x * 128;
    switch (blockIdx.z) {
        case 0: gemm_body(dsm, Ah0, Al0, Wh0, Wl0, b0, nullptr, Ch0, Cl0, 0, sc0, m0, n0); break;
        case 1: gemm_body(dsm, Ah1, Al1, Wh1, Wl1, b1, nullptr, Ch1, Cl1, 0, 1.0f, m0, n0); break;
        default: gemm_body(dsm, Ah2, Al2, Wh2, Wl2, b2, nullptr, Ch2, Cl2, 0, 1.0f, m0, n0); break;
    }
}

__global__ __launch_bounds__(256)
void gemm_o(const __nv_bfloat16* Ah, const __nv_bfloat16* Al,
            const __nv_bfloat16* Wh, const __nv_bfloat16* Wl,
            const float* bias, float* Cf)
{
    extern __shared__ __align__(16) char dsm[];
    gemm_body(dsm, Ah, Al, Wh, Wl, bias, Cf, nullptr, nullptr, 2, 1.0f,
              blockIdx.y * 128, blockIdx.x * 128);
}

// ---------------------------------------------------------------------------
// Tensor-core flash attention (R8 structure). Mask read directly from gmem
// (pre-packed bytes, L2-resident) -> smem drops to 72KB -> 3 CTAs/SM.
// ---------------------------------------------------------------------------
#define AST 144                 // bytes per K/V smem row (128B data + 16B pad)
#define KVSTAGE (4 * 64 * AST)  // 36864 per stage (Kh,Kl,Vh,Vl)
#define ATTN_SMEM (2 * KVSTAGE) // 73728

__global__ __launch_bounds__(128, 3)
void attn_mma(const __nv_bfloat16* __restrict__ qh_g, const __nv_bfloat16* __restrict__ ql_g,
              const __nv_bfloat16* __restrict__ kh_g, const __nv_bfloat16* __restrict__ kl_g,
              const __nv_bfloat16* __restrict__ vh_g, const __nv_bfloat16* __restrict__ vl_g,
              const unsigned char* __restrict__ maskp, const float* __restrict__ graph,
              __nv_bfloat16* __restrict__ ctxh, __nv_bfloat16* __restrict__ ctxl)
{
    extern __shared__ __align__(16) char dsm[];

    const int tid = threadIdx.x;
    const int w = tid >> 5, lane = tid & 31;
    const int g = lane >> 2, t = lane & 3;
    const int sub = lane >> 3;
    const int hh = blockIdx.y, b = blockIdx.z;
    const int q0 = blockIdx.x * 64;
    const bool lastH = (hh == Hn - 1);

    const size_t hoff = (size_t)((b * Hn + hh) * Sn) * DHn;
    const unsigned char* mbase = maskp + (size_t)(b * Sn) * Sn;
    const float* gbase = graph + (size_t)(b * Sn) * Sn;

    unsigned qh[4][4], ql[4][4];
    {
        const __nv_bfloat16* qb_h = qh_g + hoff + (size_t)(q0 + w * 16) * DHn;
        const __nv_bfloat16* qb_l = ql_g + hoff + (size_t)(q0 + w * 16) * DHn;
        #pragma unroll
        for (int kt = 0; kt < 4; kt++) {
            int c0 = kt * 16 + 2 * t;
            qh[kt][0] = *(const unsigned*)(qb_h + (size_t)g * DHn + c0);
            qh[kt][1] = *(const unsigned*)(qb_h + (size_t)(g + 8) * DHn + c0);
            qh[kt][2] = *(const unsigned*)(qb_h + (size_t)g * DHn + c0 + 8);
            qh[kt][3] = *(const unsigned*)(qb_h + (size_t)(g + 8) * DHn + c0 + 8);
            ql[kt][0] = *(const unsigned*)(qb_l + (size_t)g * DHn + c0);
            ql[kt][1] = *(const unsigned*)(qb_l + (size_t)(g + 8) * DHn + c0);
            ql[kt][2] = *(const unsigned*)(qb_l + (size_t)g * DHn + c0 + 8);
            ql[kt][3] = *(const unsigned*)(qb_l + (size_t)(g + 8) * DHn + c0 + 8);
        }
    }

    float O[8][4];
    #pragma unroll
    for (int nt = 0; nt < 8; nt++)
        #pragma unroll
        for (int e = 0; e < 4; e++) O[nt][e] = 0.f;
    float lA = 0.f, lB = 0.f;
    const int rA = w * 16 + g, rB = rA + 8;

    auto issue = [&](int kt16) {
        const int buf = kt16 & 1;
        char* st = dsm + buf * KVSTAGE;
        const int kt0 = kt16 * 64;
        #pragma unroll
        for (int i = 0; i < 4; i++) {
            int cc = i * 128 + tid;
            int r = cc >> 3, off = cc & 7;
            size_t gsrc = hoff + (size_t)(kt0 + r) * DHn + off * 8;
            CPA16(smem_u32(st + r * AST + off * 16),                kh_g + gsrc);
            CPA16(smem_u32(st + 64 * AST + r * AST + off * 16),     kl_g + gsrc);
            CPA16(smem_u32(st + 2 * 64 * AST + r * AST + off * 16), vh_g + gsrc);
            CPA16(smem_u32(st + 3 * 64 * AST + r * AST + off * 16), vl_g + gsrc);
        }
    };

    issue(0);
    CPA_COMMIT();

    for (int kt16 = 0; kt16 < 16; kt16++) {
        if (kt16 + 1 < 16) { issue(kt16 + 1); CPA_COMMIT(); CPA_WAIT1(); }
        else               { CPA_WAIT0(); }
        __syncthreads();

        char* st = dsm + (kt16 & 1) * KVSTAGE;
        char* sKh = st;
        char* sKl = st + 64 * AST;
        char* sVh = st + 2 * 64 * AST;
        char* sVl = st + 3 * 64 * AST;
        const int kt0 = kt16 * 64;

        // prefetch mask bytes for this tile (gmem, L2-resident) — overlaps S mma
        uchar2 mA8[8], mB8[8];
        {
            const unsigned char* mrA = mbase + (size_t)(q0 + rA) * Sn + kt0;
            const unsigned char* mrB = mbase + (size_t)(q0 + rB) * Sn + kt0;
            #pragma unroll
            for (int nt = 0; nt < 8; nt++) {
                const int col = nt * 8 + 2 * t;
                mA8[nt] = *(const uchar2*)(mrA + col);
                mB8[nt] = *(const uchar2*)(mrB + col);
            }
        }

        float S[8][4];
        #pragma unroll
        for (int nt = 0; nt < 8; nt++)
            #pragma unroll
            for (int e = 0; e < 4; e++) S[nt][e] = 0.f;
        #pragma unroll
        for (int kt = 0; kt < 4; kt++) {
            unsigned th[4][4], tl[4][4];
            #pragma unroll
            for (int ntp = 0; ntp < 4; ntp++) {
                int r = (ntp * 2 + (sub >> 1)) * 8 + (lane & 7);
                int kb = kt * 32 + (sub & 1) * 16;
                ldsm4(th[ntp], smem_u32(sKh + r * AST + kb));
                ldsm4(tl[ntp], smem_u32(sKl + r * AST + kb));
            }
            #pragma unroll
            for (int ntp = 0; ntp < 4; ntp++) {
                mma16816(S[2 * ntp],     qh[kt], th[ntp]);
                mma16816(S[2 * ntp + 1], qh[kt], th[ntp] + 2);
            }
            #pragma unroll
            for (int ntp = 0; ntp < 4; ntp++) {
                mma16816(S[2 * ntp],     qh[kt], tl[ntp]);
                mma16816(S[2 * ntp + 1], qh[kt], tl[ntp] + 2);
            }
            #pragma unroll
            for (int ntp = 0; ntp < 4; ntp++) {
                mma16816(S[2 * ntp],     ql[kt], th[ntp]);
                mma16816(S[2 * ntp + 1], ql[kt], th[ntp] + 2);
            }
        }

        float2 gA[8], gB[8];
        if (lastH) {
            #pragma unroll
            for (int nt = 0; nt < 8; nt++) {
                int col = kt0 + nt * 8 + 2 * t;
                gA[nt] = *(const float2*)(gbase + (size_t)(q0 + rA) * Sn + col);
                gB[nt] = *(const float2*)(gbase + (size_t)(q0 + rB) * Sn + col);
            }
        }

        float la = 0.f, lb = 0.f;
        #pragma unroll
        for (int nt = 0; nt < 8; nt++) {
            float p0 = exp2p(S[nt][0]);
            float p1 = exp2p(S[nt][1]);
            float p2 = exp2p(S[nt][2]);
            float p3 = exp2p(S[nt][3]);
            if (mA8[nt].x) p0 = 0.f;
            if (mA8[nt].y) p1 = 0.f;
            if (mB8[nt].x) p2 = 0.f;
            if (mB8[nt].y) p3 = 0.f;
            if (lastH) {
                p0 *= gA[nt].x; p1 *= gA[nt].y;
                p2 *= gB[nt].x; p3 *= gB[nt].y;
            }
            S[nt][0] = p0; S[nt][1] = p1; S[nt][2] = p2; S[nt][3] = p3;
            la += p0 + p1; lb += p2 + p3;
        }
        lA += la; lB += lb;

        #pragma unroll
        for (int kt = 0; kt < 4; kt++) {
            unsigned ph[4], pl[4];
            split_pack(S[2 * kt][0],     S[2 * kt][1],     ph[0], pl[0]);
            split_pack(S[2 * kt][2],     S[2 * kt][3],     ph[1], pl[1]);
            split_pack(S[2 * kt + 1][0], S[2 * kt + 1][1], ph[2], pl[2]);
            split_pack(S[2 * kt + 1][2], S[2 * kt + 1][3], ph[3], pl[3]);
            unsigned th[4][4], tl[4][4];
            #pragma unroll
            for (int ntp = 0; ntp < 4; ntp++) {
                int r = kt * 16 + (sub & 1) * 8 + (lane & 7);
                int cb = (2 * ntp + (sub >> 1)) * 16;
                ldsm4t(th[ntp], smem_u32(sVh + r * AST + cb));
                ldsm4t(tl[ntp], smem_u32(sVl + r * AST + cb));
            }
            #pragma unroll
            for (int ntp = 0; ntp < 4; ntp++) {
                mma16816(O[2 * ntp],     ph, th[ntp]);
                mma16816(O[2 * ntp + 1], ph, th[ntp] + 2);
            }
            #pragma unroll
            for (int ntp = 0; ntp < 4; ntp++) {
                mma16816(O[2 * ntp],     ph, tl[ntp]);
                mma16816(O[2 * ntp + 1], ph, tl[ntp] + 2);
            }
            #pragma unroll
            for (int ntp = 0; ntp < 4; ntp++) {
                mma16816(O[2 * ntp],     pl, th[ntp]);
                mma16816(O[2 * ntp + 1], pl, th[ntp] + 2);
            }
        }
        __syncthreads();
    }

    lA += __shfl_xor_sync(0xffffffff, lA, 1);
    lA += __shfl_xor_sync(0xffffffff, lA, 2);
    lB += __shfl_xor_sync(0xffffffff, lB, 1);
    lB += __shfl_xor_sync(0xffffffff, lB, 2);
    const float invA = 1.f / lA, invB = 1.f / lB;

    const int rowA = q0 + rA, rowB = q0 + rB;
    #pragma unroll
    for (int nt = 0; nt < 8; nt++) {
        const int col = hh * DHn + nt * 8 + 2 * t;
        unsigned hw, lw;
        split_pack(O[nt][0] * invA, O[nt][1] * invA, hw, lw);
        *(unsigned*)(ctxh + (size_t)(b * Sn + rowA) * Dn + col) = hw;
        *(unsigned*)(ctxl + (size_t)(b * Sn + rowA) * Dn + col) = lw;
        split_pack(O[nt][2] * invB, O[nt][3] * invB, hw, lw);
        *(unsigned*)(ctxh + (size_t)(b * Sn + rowB) * Dn + col) = hw;
        *(unsigned*)(ctxl + (size_t)(b * Sn + rowB) * Dn + col) = lw;
    }
}

// ---------------------------------------------------------------------------
// Launch: fork-join second stream for mask pack + Wo split (overlaps with
// input/weight splits and gemm_qkv).
// ---------------------------------------------------------------------------
extern "C" void kernel_launch(void* const* d_in, const int* in_sizes, int n_in,
                              void* d_out, int out_size)
{
    const float* key   = (const float*)d_in[0];
    const float* value = (const float*)d_in[1];
    const float* query = (const float*)d_in[2];
    const int*   mask  = (const int*)d_in[3];
    const float* graph = (const float*)d_in[4];
    const float* Wq = (const float*)d_in[5];
    const float* bq = (const float*)d_in[6];
    const float* Wk = (const float*)d_in[7];
    const float* bk = (const float*)d_in[8];
    const float* Wv = (const float*)d_in[9];
    const float* bv = (const float*)d_in[10];
    const float* Wo = (const float*)d_in[11];
    const float* bo = (const float*)d_in[12];
    float* out = (float*)d_out;

    static cudaStream_t s2 = nullptr;
    static cudaEvent_t evFork = nullptr, evJoin = nullptr;
    static int inited = 0;
    if (!inited) {
        cudaFuncSetAttribute(gemm_qkv, cudaFuncAttributeMaxDynamicSharedMemorySize, 81920);
        cudaFuncSetAttribute(gemm_o, cudaFuncAttributeMaxDynamicSharedMemorySize, 81920);
        cudaFuncSetAttribute(attn_mma, cudaFuncAttributeMaxDynamicSharedMemorySize, ATTN_SMEM);
        cudaStreamCreateWithFlags(&s2, cudaStreamNonBlocking);
        cudaEventCreateWithFlags(&evFork, cudaEventDisableTiming);
        cudaEventCreateWithFlags(&evJoin, cudaEventDisableTiming);
        inited = 1;
    }

    #define SYM(p, s) void* p; cudaGetSymbolAddress(&p, s)
    SYM(iqh, gin_qh); SYM(iql, gin_ql);
    SYM(ikh, gin_kh); SYM(ikl, gin_kl);
    SYM(ivh, gin_vh); SYM(ivl, gin_vl);
    SYM(wqh, gWqh); SYM(wql, gWql);
    SYM(wkh, gWkh); SYM(wkl, gWkl);
    SYM(wvh, gWvh); SYM(wvl, gWvl);
    SYM(woh, gWoh); SYM(wol, gWol);
    SYM(pqh, g_qh); SYM(pql, g_ql);
    SYM(pkh, g_kh); SYM(pkl, g_kl);
    SYM(pvh, g_vh); SYM(pvl, g_vl);
    SYM(cxh, g_ctxh); SYM(cxl, g_ctxl);
    SYM(mpk, g_mask);
    #undef SYM

    typedef __nv_bfloat16 bf;
    const int nIn = Mn * Dn / 2, nW = Dn * Dn / 2;

    // fork side stream: mask pack + Wo split (no upstream deps)
    cudaEventRecord(evFork, 0);
    cudaStreamWaitEvent(s2, evFork, 0);
    const int nM4 = Bn * Sn * Sn / 4;
    pack_mask<<<(nM4 + 255) / 256, 256, 0, s2>>>((const int4*)mask, (uchar4*)mpk, nM4);
    split_in1<<<(nW + 255) / 256, 256, 0, s2>>>(Wo, (bf*)woh, (bf*)wol, nW);
    cudaEventRecord(evJoin, s2);

    // main stream: input + QKV-weight splits, then projections
    split_in3<<<dim3((nIn + 255) / 256, 3), 256>>>(
        query, key, value,
        (bf*)iqh, (bf*)iql, (bf*)ikh, (bf*)ikl, (bf*)ivh, (bf*)ivl, nIn);
    split_in3<<<dim3((nW + 255) / 256, 3), 256>>>(
        Wq, Wk, Wv,
        (bf*)wqh, (bf*)wql, (bf*)wkh, (bf*)wkl, (bf*)wvh, (bf*)wvl, nW);

    const float QSCALE = 0.125f * 1.4426950408889634f;   // fold log2e into Q
    dim3 qkvgrid(Dn / 128, Mn / 128, 3);   // (8, 64, 3)
    gemm_qkv<<<qkvgrid, 256, 81920>>>(
        (bf*)iqh, (bf*)iql, (bf*)ikh, (bf*)ikl, (bf*)ivh, (bf*)ivl,
        (bf*)wqh, (bf*)wql, (bf*)wkh, (bf*)wkl, (bf*)wvh, (bf*)wvl,
        bq, bk, bv,
        (bf*)pqh, (bf*)pql, (bf*)pkh, (bf*)pkl, (bf*)pvh, (bf*)pvl,
        QSCALE);

    // join: attn needs packed mask; gemm_o needs Wo split
    cudaStreamWaitEvent(0, evJoin, 0);

    attn_mma<<<dim3(Sn / 64, Hn, Bn), 128, ATTN_SMEM>>>(
        (const bf*)pqh, (const bf*)pql, (const bf*)pkh, (const bf*)pkl,
        (const bf*)pvh, (const bf*)pvl, (const unsigned char*)mpk, graph,
        (bf*)cxh, (bf*)cxl);

    gemm_o<<<dim3(Dn / 128, Mn / 128), 256, 81920>>>(
        (const bf*)cxh, (const bf*)cxl, (bf*)woh, (bf*)wol, bo, out);
}

// round 17
// speedup vs baseline: 1.6058x; 1.0055x over previous
#include <cuda_runtime.h>
#include <cuda_bf16.h>
#include <math_constants.h>

#define Bn  8
#define Sn  1024
#define Dn  1024
#define Hn  16
#define DHn 64
#define Mn  (Bn * Sn)   // 8192

// ---------------------------------------------------------------------------
// Device-global scratch
// ---------------------------------------------------------------------------
__device__ __nv_bfloat16 gin_qh[Mn * Dn], gin_ql[Mn * Dn];
__device__ __nv_bfloat16 gin_kh[Mn * Dn], gin_kl[Mn * Dn];
__device__ __nv_bfloat16 gin_vh[Mn * Dn], gin_vl[Mn * Dn];
__device__ __nv_bfloat16 gWqh[Dn * Dn], gWql[Dn * Dn];
__device__ __nv_bfloat16 gWkh[Dn * Dn], gWkl[Dn * Dn];
__device__ __nv_bfloat16 gWvh[Dn * Dn], gWvl[Dn * Dn];
__device__ __nv_bfloat16 gWoh[Dn * Dn], gWol[Dn * Dn];
__device__ __nv_bfloat16 g_qh[Mn * Dn], g_ql[Mn * Dn];   // [B,H,S,DH]
__device__ __nv_bfloat16 g_kh[Mn * Dn], g_kl[Mn * Dn];
__device__ __nv_bfloat16 g_vh[Mn * Dn], g_vl[Mn * Dn];
__device__ __nv_bfloat16 g_ctxh[Mn * Dn], g_ctxl[Mn * Dn]; // [B,S,D]
__device__ unsigned long long g_mask64[Bn * Sn * Sn / 64]; // bitpacked mask

// ---------------------------------------------------------------------------
// helpers
// ---------------------------------------------------------------------------
__device__ __forceinline__ unsigned smem_u32(const void* p) {
    return (unsigned)__cvta_generic_to_shared(p);
}
__device__ __forceinline__ void mma16816(float* c, const unsigned* a, const unsigned* b) {
    asm volatile(
        "mma.sync.aligned.m16n8k16.row.col.f32.bf16.bf16.f32 "
        "{%0,%1,%2,%3},{%4,%5,%6,%7},{%8,%9},{%0,%1,%2,%3};\n"
        : "+f"(c[0]), "+f"(c[1]), "+f"(c[2]), "+f"(c[3])
        : "r"(a[0]), "r"(a[1]), "r"(a[2]), "r"(a[3]), "r"(b[0]), "r"(b[1]));
}
__device__ __forceinline__ void ldsm4(unsigned* r, unsigned addr) {
    asm volatile("ldmatrix.sync.aligned.m8n8.x4.shared.b16 {%0,%1,%2,%3},[%4];\n"
                 : "=r"(r[0]), "=r"(r[1]), "=r"(r[2]), "=r"(r[3]) : "r"(addr));
}
__device__ __forceinline__ void ldsm4t(unsigned* r, unsigned addr) {
    asm volatile("ldmatrix.sync.aligned.m8n8.x4.trans.shared.b16 {%0,%1,%2,%3},[%4];\n"
                 : "=r"(r[0]), "=r"(r[1]), "=r"(r[2]), "=r"(r[3]) : "r"(addr));
}
__device__ __forceinline__ void split_pack(float x, float y, unsigned& hi, unsigned& lo) {
    __nv_bfloat16 hx = __float2bfloat16(x);
    __nv_bfloat16 hy = __float2bfloat16(y);
    float rx = x - __bfloat162float(hx);
    float ry = y - __bfloat162float(hy);
    __nv_bfloat162 h; h.x = hx; h.y = hy;
    __nv_bfloat162 l; l.x = __float2bfloat16(rx); l.y = __float2bfloat16(ry);
    hi = *(unsigned*)&h;
    lo = *(unsigned*)&l;
}
// fast 2^y, FMA-only (no MUFU)
__device__ __forceinline__ float exp2p(float y) {
    y = fmaxf(fminf(y, 60.f), -60.f);
    float z = y + 12582912.f;              // 1.5*2^23
    int i = __float_as_int(z) << 23;
    float f = y - (z - 12582912.f);
    float p = 1.3333558e-3f;
    p = fmaf(p, f, 9.6181291e-3f);
    p = fmaf(p, f, 5.5504109e-2f);
    p = fmaf(p, f, 2.4022651e-1f);
    p = fmaf(p, f, 6.9314718e-1f);
    p = fmaf(p, f, 1.0f);
    return __int_as_float(__float_as_int(p) + i);
}
#define CPA16(smem, gmem) asm volatile("cp.async.cg.shared.global [%0], [%1], 16;\n" :: "r"(smem), "l"(gmem))
#define CPA_COMMIT()      asm volatile("cp.async.commit_group;\n")
#define CPA_WAIT0()       asm volatile("cp.async.wait_group 0;\n" ::: "memory")
#define CPA_WAIT1()       asm volatile("cp.async.wait_group 1;\n" ::: "memory")

// ---------------------------------------------------------------------------
// Pre-split kernels + bitpack mask
// ---------------------------------------------------------------------------
__device__ __forceinline__ void do_split(const float* src, __nv_bfloat16* hi,
                                         __nv_bfloat16* lo, int i) {
    float2 v = ((const float2*)src)[i];
    unsigned h, l;
    split_pack(v.x, v.y, h, l);
    ((unsigned*)hi)[i] = h;
    ((unsigned*)lo)[i] = l;
}
__global__ void split_in3(const float* __restrict__ s0, const float* __restrict__ s1,
                          const float* __restrict__ s2,
                          __nv_bfloat16* h0, __nv_bfloat16* l0,
                          __nv_bfloat16* h1, __nv_bfloat16* l1,
                          __nv_bfloat16* h2, __nv_bfloat16* l2, int n2)
{
    int i = blockIdx.x * blockDim.x + threadIdx.x;
    if (i >= n2) return;
    switch (blockIdx.y) {
        case 0: do_split(s0, h0, l0, i); break;
        case 1: do_split(s1, h1, l1, i); break;
        default: do_split(s2, h2, l2, i); break;
    }
}
__global__ void split_in4(const float* __restrict__ s0, const float* __restrict__ s1,
                          const float* __restrict__ s2, const float* __restrict__ s3,
                          __nv_bfloat16* h0, __nv_bfloat16* l0,
                          __nv_bfloat16* h1, __nv_bfloat16* l1,
                          __nv_bfloat16* h2, __nv_bfloat16* l2,
                          __nv_bfloat16* h3, __nv_bfloat16* l3, int n2)
{
    int i = blockIdx.x * blockDim.x + threadIdx.x;
    if (i >= n2) return;
    switch (blockIdx.y) {
        case 0: do_split(s0, h0, l0, i); break;
        case 1: do_split(s1, h1, l1, i); break;
        case 2: do_split(s2, h2, l2, i); break;
        default: do_split(s3, h3, l3, i); break;
    }
}
// pack 64 mask ints -> one u64 (bit j = key j masked). warp-cooperative, coalesced.
__global__ void pack_mask64(const int* __restrict__ m, unsigned long long* __restrict__ o,
                            int n64)
{
    int w = (blockIdx.x * blockDim.x + threadIdx.x) >> 5;
    int lane = threadIdx.x & 31;
    if (w >= n64) return;
    const int* src = m + (size_t)w * 64;
    unsigned lo = __ballot_sync(0xffffffffu, src[lane] != 0);
    unsigned hi = __ballot_sync(0xffffffffu, src[32 + lane] != 0);
    if (lane == 0) o[w] = ((unsigned long long)hi << 32) | lo;
}

// ---------------------------------------------------------------------------
// Split-bf16 (3x) GEMM body (EXACT R8 version: 128x128, BK=32, 256 thr,
// 2x4 warp grid, 2 CTAs/SM, cp.async double-buffered, term-outer order).
// ---------------------------------------------------------------------------
#define GST 80  // bytes per smem row (64B data + 16B pad)

__device__ __forceinline__
void gemm_body(char* dsm,
               const __nv_bfloat16* __restrict__ Ahi, const __nv_bfloat16* __restrict__ Alo,
               const __nv_bfloat16* __restrict__ Whi, const __nv_bfloat16* __restrict__ Wlo,
               const float* __restrict__ bias,
               float* __restrict__ Cf,
               __nv_bfloat16* __restrict__ Ch, __nv_bfloat16* __restrict__ Cl,
               int mode, float scale, int m0, int n0)
{
    const int tid = threadIdx.x;
    const int wid = tid >> 5, lane = tid & 31;
    const int wm = wid >> 2, wn = wid & 3;
    const int g = lane >> 2, t = lane & 3;
    const int sub = lane >> 3;

    float c[4][4][4];
    #pragma unroll
    for (int mt = 0; mt < 4; mt++)
        #pragma unroll
        for (int nt = 0; nt < 4; nt++)
            #pragma unroll
            for (int e = 0; e < 4; e++) c[mt][nt][e] = 0.f;

    auto issue = [&](int k0, int buf) {
        char* st = dsm + buf * 40960;
        #pragma unroll
        for (int i = 0; i < 2; i++) {
            int cc = i * 256 + tid;
            int r = cc >> 2, off = cc & 3;
            size_t ga = (size_t)(m0 + r) * Dn + k0 + off * 8;
            size_t gw = (size_t)(n0 + r) * Dn + k0 + off * 8;
            unsigned sa = smem_u32(st + r * GST + off * 16);
            CPA16(sa,         Ahi + ga);
            CPA16(sa + 10240, Alo + ga);
            CPA16(sa + 20480, Whi + gw);
            CPA16(sa + 30720, Wlo + gw);
        }
    };

    issue(0, 0);
    CPA_COMMIT();

    for (int it = 0; it < Dn / 32; it++) {
        CPA_WAIT0();
        __syncthreads();
        if (it + 1 < Dn / 32) { issue((it + 1) * 32, (it + 1) & 1); CPA_COMMIT(); }

        char* st = dsm + (it & 1) * 40960;
        char* sAh = st; char* sAl = st + 10240;
        char* sWh = st + 20480; char* sWl = st + 30720;

        #pragma unroll
        for (int kt = 0; kt < 2; kt++) {
            unsigned ah[4][4], al[4][4], bh[4][2], bl[4][2];
            #pragma unroll
            for (int mt = 0; mt < 4; mt++) {
                int r = wm * 64 + mt * 16 + (lane & 7) + (sub & 1) * 8;
                int kb = kt * 32 + (sub >> 1) * 16;
                ldsm4(ah[mt], smem_u32(sAh + r * GST + kb));
                ldsm4(al[mt], smem_u32(sAl + r * GST + kb));
            }
            #pragma unroll
            for (int ntp = 0; ntp < 2; ntp++) {
                int r = wn * 32 + (ntp * 2 + (sub >> 1)) * 8 + (lane & 7);
                int kb = kt * 32 + (sub & 1) * 16;
                unsigned tmp[4];
                ldsm4(tmp, smem_u32(sWh + r * GST + kb));
                bh[2 * ntp][0] = tmp[0]; bh[2 * ntp][1] = tmp[1];
                bh[2 * ntp + 1][0] = tmp[2]; bh[2 * ntp + 1][1] = tmp[3];
                ldsm4(tmp, smem_u32(sWl + r * GST + kb));
                bl[2 * ntp][0] = tmp[0]; bl[2 * ntp][1] = tmp[1];
                bl[2 * ntp + 1][0] = tmp[2]; bl[2 * ntp + 1][1] = tmp[3];
            }
            #pragma unroll
            for (int mt = 0; mt < 4; mt++)
                #pragma unroll
                for (int nt = 0; nt < 4; nt++)
                    mma16816(c[mt][nt], ah[mt], bh[nt]);
            #pragma unroll
            for (int mt = 0; mt < 4; mt++)
                #pragma unroll
                for (int nt = 0; nt < 4; nt++)
                    mma16816(c[mt][nt], ah[mt], bl[nt]);
            #pragma unroll
            for (int mt = 0; mt < 4; mt++)
                #pragma unroll
                for (int nt = 0; nt < 4; nt++)
                    mma16816(c[mt][nt], al[mt], bh[nt]);
        }
    }

    #pragma unroll
    for (int mt = 0; mt < 4; mt++) {
        #pragma unroll
        for (int nt = 0; nt < 4; nt++) {
            const int row = m0 + wm * 64 + mt * 16 + g;
            const int col = n0 + wn * 32 + nt * 8 + 2 * t;
            const float b0 = bias[col], b1 = bias[col + 1];
            #pragma unroll
            for (int half = 0; half < 2; half++) {
                const int r = row + half * 8;
                const float v0 = (c[mt][nt][half * 2 + 0] + b0) * scale;
                const float v1 = (c[mt][nt][half * 2 + 1] + b1) * scale;
                if (mode == 2) {
                    *(float2*)(Cf + (size_t)r * Dn + col) = make_float2(v0, v1);
                } else {
                    const int bb = r >> 10, s = r & 1023;
                    const int hh = col >> 6, d = col & 63;
                    size_t idx = (((size_t)(bb * Hn + hh) * Sn + s) * DHn) + d;
                    unsigned hw, lw;
                    split_pack(v0, v1, hw, lw);
                    *(unsigned*)(Ch + idx) = hw;
                    *(unsigned*)(Cl + idx) = lw;
                }
            }
        }
    }
}

// fused Q/K/V projections: blockIdx.z selects the matmul
__global__ __launch_bounds__(256)
void gemm_qkv(const __nv_bfloat16* Ah0, const __nv_bfloat16* Al0,
              const __nv_bfloat16* Ah1, const __nv_bfloat16* Al1,
              const __nv_bfloat16* Ah2, const __nv_bfloat16* Al2,
              const __nv_bfloat16* Wh0, const __nv_bfloat16* Wl0,
              const __nv_bfloat16* Wh1, const __nv_bfloat16* Wl1,
              const __nv_bfloat16* Wh2, const __nv_bfloat16* Wl2,
              const float* b0, const float* b1, const float* b2,
              __nv_bfloat16* Ch0, __nv_bfloat16* Cl0,
              __nv_bfloat16* Ch1, __nv_bfloat16* Cl1,
              __nv_bfloat16* Ch2, __nv_bfloat16* Cl2,
              float sc0)
{
    extern __shared__ __align__(16) char dsm[];
    const int m0 = blockIdx.y * 128, n0 = blockIdx.x * 128;
    switch (blockIdx.z) {
        case 0: gemm_body(dsm, Ah0, Al0, Wh0, Wl0, b0, nullptr, Ch0, Cl0, 0, sc0, m0, n0); break;
        case 1: gemm_body(dsm, Ah1, Al1, Wh1, Wl1, b1, nullptr, Ch1, Cl1, 0, 1.0f, m0, n0); break;
        default: gemm_body(dsm, Ah2, Al2, Wh2, Wl2, b2, nullptr, Ch2, Cl2, 0, 1.0f, m0, n0); break;
    }
}

__global__ __launch_bounds__(256)
void gemm_o(const __nv_bfloat16* Ah, const __nv_bfloat16* Al,
            const __nv_bfloat16* Wh, const __nv_bfloat16* Wl,
            const float* bias, float* Cf)
{
    extern __shared__ __align__(16) char dsm[];
    gemm_body(dsm, Ah, Al, Wh, Wl, bias, Cf, nullptr, nullptr, 2, 1.0f,
              blockIdx.y * 128, blockIdx.x * 128);
}

// ---------------------------------------------------------------------------
// Tensor-core flash attention (R8 structure) with bitpacked mask from gmem
// (2 u64 loads per thread per tile, L2-resident, prefetched before S-mma)
// and graph loaded inline. smem = K/V double-buffer only (72KB) -> 3 CTAs/SM.
// ---------------------------------------------------------------------------
#define AST 144                 // bytes per K/V smem row (128B data + 16B pad)
#define KVSTAGE (4 * 64 * AST)  // 36864 per stage (Kh,Kl,Vh,Vl)
#define ATTN_SMEM (2 * KVSTAGE) // 73728

__global__ __launch_bounds__(128, 3)
void attn_mma(const __nv_bfloat16* __restrict__ qh_g, const __nv_bfloat16* __restrict__ ql_g,
              const __nv_bfloat16* __restrict__ kh_g, const __nv_bfloat16* __restrict__ kl_g,
              const __nv_bfloat16* __restrict__ vh_g, const __nv_bfloat16* __restrict__ vl_g,
              const unsigned long long* __restrict__ mask64, const float* __restrict__ graph,
              __nv_bfloat16* __restrict__ ctxh, __nv_bfloat16* __restrict__ ctxl)
{
    extern __shared__ __align__(16) char dsm[];

    const int tid = threadIdx.x;
    const int w = tid >> 5, lane = tid & 31;
    const int g = lane >> 2, t = lane & 3;
    const int sub = lane >> 3;
    const int hh = blockIdx.y, b = blockIdx.z;
    const int q0 = blockIdx.x * 64;
    const bool lastH = (hh == Hn - 1);

    const size_t hoff = (size_t)((b * Hn + hh) * Sn) * DHn;
    const float* gbase = graph + (size_t)(b * Sn) * Sn;

    unsigned qh[4][4], ql[4][4];
    {
        const __nv_bfloat16* qb_h = qh_g + hoff + (size_t)(q0 + w * 16) * DHn;
        const __nv_bfloat16* qb_l = ql_g + hoff + (size_t)(q0 + w * 16) * DHn;
        #pragma unroll
        for (int kt = 0; kt < 4; kt++) {
            int c0 = kt * 16 + 2 * t;
            qh[kt][0] = *(const unsigned*)(qb_h + (size_t)g * DHn + c0);
            qh[kt][1] = *(const unsigned*)(qb_h + (size_t)(g + 8) * DHn + c0);
            qh[kt][2] = *(const unsigned*)(qb_h + (size_t)g * DHn + c0 + 8);
            qh[kt][3] = *(const unsigned*)(qb_h + (size_t)(g + 8) * DHn + c0 + 8);
            ql[kt][0] = *(const unsigned*)(qb_l + (size_t)g * DHn + c0);
            ql[kt][1] = *(const unsigned*)(qb_l + (size_t)(g + 8) * DHn + c0);
            ql[kt][2] = *(const unsigned*)(qb_l + (size_t)g * DHn + c0 + 8);
            ql[kt][3] = *(const unsigned*)(qb_l + (size_t)(g + 8) * DHn + c0 + 8);
        }
    }

    float O[8][4];
    #pragma unroll
    for (int nt = 0; nt < 8; nt++)
        #pragma unroll
        for (int e = 0; e < 4; e++) O[nt][e] = 0.f;
    float lA = 0.f, lB = 0.f;
    const int rA = w * 16 + g, rB = rA + 8;

    // bitmask row bases (u64 index): row r, chunk kt16 -> (b*Sn + q0 + r)*16 + kt16
    const unsigned long long* mrowA = mask64 + ((size_t)(b * Sn) + q0 + rA) * 16;
    const unsigned long long* mrowB = mask64 + ((size_t)(b * Sn) + q0 + rB) * 16;

    auto issue = [&](int kt16) {
        const int buf = kt16 & 1;
        char* st = dsm + buf * KVSTAGE;
        const int kt0 = kt16 * 64;
        #pragma unroll
        for (int i = 0; i < 4; i++) {
            int cc = i * 128 + tid;
            int r = cc >> 3, off = cc & 7;
            size_t gsrc = hoff + (size_t)(kt0 + r) * DHn + off * 8;
            CPA16(smem_u32(st + r * AST + off * 16),                kh_g + gsrc);
            CPA16(smem_u32(st + 64 * AST + r * AST + off * 16),     kl_g + gsrc);
            CPA16(smem_u32(st + 2 * 64 * AST + r * AST + off * 16), vh_g + gsrc);
            CPA16(smem_u32(st + 3 * 64 * AST + r * AST + off * 16), vl_g + gsrc);
        }
    };

    issue(0);
    CPA_COMMIT();

    for (int kt16 = 0; kt16 < 16; kt16++) {
        if (kt16 + 1 < 16) { issue(kt16 + 1); CPA_COMMIT(); CPA_WAIT1(); }
        else               { CPA_WAIT0(); }
        __syncthreads();

        char* st = dsm + (kt16 & 1) * KVSTAGE;
        char* sKh = st;
        char* sKl = st + 64 * AST;
        char* sVh = st + 2 * 64 * AST;
        char* sVl = st + 3 * 64 * AST;
        const int kt0 = kt16 * 64;

        // prefetch bitmask words (L2-resident) — latency hidden behind S mma
        const unsigned long long MA = mrowA[kt16];
        const unsigned long long MB = mrowB[kt16];

        float S[8][4];
        #pragma unroll
        for (int nt = 0; nt < 8; nt++)
            #pragma unroll
            for (int e = 0; e < 4; e++) S[nt][e] = 0.f;
        #pragma unroll
        for (int kt = 0; kt < 4; kt++) {
            unsigned th[4][4], tl[4][4];
            #pragma unroll
            for (int ntp = 0; ntp < 4; ntp++) {
                int r = (ntp * 2 + (sub >> 1)) * 8 + (lane & 7);
                int kb = kt * 32 + (sub & 1) * 16;
                ldsm4(th[ntp], smem_u32(sKh + r * AST + kb));
                ldsm4(tl[ntp], smem_u32(sKl + r * AST + kb));
            }
            #pragma unroll
            for (int ntp = 0; ntp < 4; ntp++) {
                mma16816(S[2 * ntp],     qh[kt], th[ntp]);
                mma16816(S[2 * ntp + 1], qh[kt], th[ntp] + 2);
            }
            #pragma unroll
            for (int ntp = 0; ntp < 4; ntp++) {
                mma16816(S[2 * ntp],     qh[kt], tl[ntp]);
                mma16816(S[2 * ntp + 1], qh[kt], tl[ntp] + 2);
            }
            #pragma unroll
            for (int ntp = 0; ntp < 4; ntp++) {
                mma16816(S[2 * ntp],     ql[kt], th[ntp]);
                mma16816(S[2 * ntp + 1], ql[kt], th[ntp] + 2);
            }
        }

        float la = 0.f, lb = 0.f;
        #pragma unroll
        for (int nt = 0; nt < 8; nt++) {
            const int col = nt * 8 + 2 * t;
            float p0 = exp2p(S[nt][0]);
            float p1 = exp2p(S[nt][1]);
            float p2 = exp2p(S[nt][2]);
            float p3 = exp2p(S[nt][3]);
            if ((MA >> col) & 1)       p0 = 0.f;
            if ((MA >> (col + 1)) & 1) p1 = 0.f;
            if ((MB >> col) & 1)       p2 = 0.f;
            if ((MB >> (col + 1)) & 1) p3 = 0.f;
            if (lastH) {
                float2 ga = *(const float2*)(gbase + (size_t)(q0 + rA) * Sn + kt0 + col);
                float2 gb = *(const float2*)(gbase + (size_t)(q0 + rB) * Sn + kt0 + col);
                p0 *= ga.x; p1 *= ga.y;
                p2 *= gb.x; p3 *= gb.y;
            }
            S[nt][0] = p0; S[nt][1] = p1; S[nt][2] = p2; S[nt][3] = p3;
            la += p0 + p1; lb += p2 + p3;
        }
        lA += la; lB += lb;

        #pragma unroll
        for (int kt = 0; kt < 4; kt++) {
            unsigned ph[4], pl[4];
            split_pack(S[2 * kt][0],     S[2 * kt][1],     ph[0], pl[0]);
            split_pack(S[2 * kt][2],     S[2 * kt][3],     ph[1], pl[1]);
            split_pack(S[2 * kt + 1][0], S[2 * kt + 1][1], ph[2], pl[2]);
            split_pack(S[2 * kt + 1][2], S[2 * kt + 1][3], ph[3], pl[3]);
            unsigned th[4][4], tl[4][4];
            #pragma unroll
            for (int ntp = 0; ntp < 4; ntp++) {
                int r = kt * 16 + (sub & 1) * 8 + (lane & 7);
                int cb = (2 * ntp + (sub >> 1)) * 16;
                ldsm4t(th[ntp], smem_u32(sVh + r * AST + cb));
                ldsm4t(tl[ntp], smem_u32(sVl + r * AST + cb));
            }
            #pragma unroll
            for (int ntp = 0; ntp < 4; ntp++) {
                mma16816(O[2 * ntp],     ph, th[ntp]);
                mma16816(O[2 * ntp + 1], ph, th[ntp] + 2);
            }
            #pragma unroll
            for (int ntp = 0; ntp < 4; ntp++) {
                mma16816(O[2 * ntp],     ph, tl[ntp]);
                mma16816(O[2 * ntp + 1], ph, tl[ntp] + 2);
            }
            #pragma unroll
            for (int ntp = 0; ntp < 4; ntp++) {
                mma16816(O[2 * ntp],     pl, th[ntp]);
                mma16816(O[2 * ntp + 1], pl, th[ntp] + 2);
            }
        }
        __syncthreads();
    }

    lA += __shfl_xor_sync(0xffffffff, lA, 1);
    lA += __shfl_xor_sync(0xffffffff, lA, 2);
    lB += __shfl_xor_sync(0xffffffff, lB, 1);
    lB += __shfl_xor_sync(0xffffffff, lB, 2);
    const float invA = 1.f / lA, invB = 1.f / lB;

    const int rowA = q0 + rA, rowB = q0 + rB;
    #pragma unroll
    for (int nt = 0; nt < 8; nt++) {
        const int col = hh * DHn + nt * 8 + 2 * t;
        unsigned hw, lw;
        split_pack(O[nt][0] * invA, O[nt][1] * invA, hw, lw);
        *(unsigned*)(ctxh + (size_t)(b * Sn + rowA) * Dn + col) = hw;
        *(unsigned*)(ctxl + (size_t)(b * Sn + rowA) * Dn + col) = lw;
        split_pack(O[nt][2] * invB, O[nt][3] * invB, hw, lw);
        *(unsigned*)(ctxh + (size_t)(b * Sn + rowB) * Dn + col) = hw;
        *(unsigned*)(ctxl + (size_t)(b * Sn + rowB) * Dn + col) = lw;
    }
}

// ---------------------------------------------------------------------------
// Launch (single stream, R8 structure)
// ---------------------------------------------------------------------------
extern "C" void kernel_launch(void* const* d_in, const int* in_sizes, int n_in,
                              void* d_out, int out_size)
{
    const float* key   = (const float*)d_in[0];
    const float* value = (const float*)d_in[1];
    const float* query = (const float*)d_in[2];
    const int*   mask  = (const int*)d_in[3];
    const float* graph = (const float*)d_in[4];
    const float* Wq = (const float*)d_in[5];
    const float* bq = (const float*)d_in[6];
    const float* Wk = (const float*)d_in[7];
    const float* bk = (const float*)d_in[8];
    const float* Wv = (const float*)d_in[9];
    const float* bv = (const float*)d_in[10];
    const float* Wo = (const float*)d_in[11];
    const float* bo = (const float*)d_in[12];
    float* out = (float*)d_out;

    static int inited = 0;
    if (!inited) {
        cudaFuncSetAttribute(gemm_qkv, cudaFuncAttributeMaxDynamicSharedMemorySize, 81920);
        cudaFuncSetAttribute(gemm_o, cudaFuncAttributeMaxDynamicSharedMemorySize, 81920);
        cudaFuncSetAttribute(attn_mma, cudaFuncAttributeMaxDynamicSharedMemorySize, ATTN_SMEM);
        inited = 1;
    }

    #define SYM(p, s) void* p; cudaGetSymbolAddress(&p, s)
    SYM(iqh, gin_qh); SYM(iql, gin_ql);
    SYM(ikh, gin_kh); SYM(ikl, gin_kl);
    SYM(ivh, gin_vh); SYM(ivl, gin_vl);
    SYM(wqh, gWqh); SYM(wql, gWql);
    SYM(wkh, gWkh); SYM(wkl, gWkl);
    SYM(wvh, gWvh); SYM(wvl, gWvl);
    SYM(woh, gWoh); SYM(wol, gWol);
    SYM(pqh, g_qh); SYM(pql, g_ql);
    SYM(pkh, g_kh); SYM(pkl, g_kl);
    SYM(pvh, g_vh); SYM(pvl, g_vl);
    SYM(cxh, g_ctxh); SYM(cxl, g_ctxl);
    SYM(mpk, g_mask64);
    #undef SYM

    typedef __nv_bfloat16 bf;
    const int nIn = Mn * Dn / 2, nW = Dn * Dn / 2;
    split_in3<<<dim3((nIn + 255) / 256, 3), 256>>>(
        query, key, value,
        (bf*)iqh, (bf*)iql, (bf*)ikh, (bf*)ikl, (bf*)ivh, (bf*)ivl, nIn);
    split_in4<<<dim3((nW + 255) / 256, 4), 256>>>(
        Wq, Wk, Wv, Wo,
        (bf*)wqh, (bf*)wql, (bf*)wkh, (bf*)wkl,
        (bf*)wvh, (bf*)wvl, (bf*)woh, (bf*)wol, nW);
    const int nM64 = Bn * Sn * Sn / 64;   // 131072
    pack_mask64<<<(nM64 * 32 + 255) / 256, 256>>>(mask, (unsigned long long*)mpk, nM64);

    const float QSCALE = 0.125f * 1.4426950408889634f;   // fold log2e into Q
    dim3 qkvgrid(Dn / 128, Mn / 128, 3);   // (8, 64, 3)
    gemm_qkv<<<qkvgrid, 256, 81920>>>(
        (bf*)iqh, (bf*)iql, (bf*)ikh, (bf*)ikl, (bf*)ivh, (bf*)ivl,
        (bf*)wqh, (bf*)wql, (bf*)wkh, (bf*)wkl, (bf*)wvh, (bf*)wvl,
        bq, bk, bv,
        (bf*)pqh, (bf*)pql, (bf*)pkh, (bf*)pkl, (bf*)pvh, (bf*)pvl,
        QSCALE);

    attn_mma<<<dim3(Sn / 64, Hn, Bn), 128, ATTN_SMEM>>>(
        (const bf*)pqh, (const bf*)pql, (const bf*)pkh, (const bf*)pkl,
        (const bf*)pvh, (const bf*)pvl, (const unsigned long long*)mpk, graph,
        (bf*)cxh, (bf*)cxl);

    gemm_o<<<dim3(Dn / 128, Mn / 128), 256, 81920>>>(
        (const bf*)cxh, (const bf*)cxl, (bf*)woh, (bf*)wol, bo, out);
}